// round 1
// baseline (speedup 1.0000x reference)
#include <cuda_runtime.h>
#include <math.h>

// Problem constants
#define BB   8
#define LQ   512
#define LKV  1024
#define DD   1024
#define HH_  16
#define HD   64
#define LN_EPS 1e-5f

// Scratch (device globals: allocation-free per harness rules)
__device__ float g_Q  [BB * LQ  * DD];            // 16 MB  (pre-scaled q proj)
__device__ float g_K  [BB * LKV * DD];            // 32 MB
__device__ float g_V  [BB * LKV * DD];            // 32 MB
__device__ float g_S  [(size_t)BB * HH_ * LQ * LKV]; // 256 MB (scores -> probs in place)
__device__ float g_CTX[BB * LQ  * DD];            // 16 MB
__device__ float g_AO [BB * LQ  * DD];            // 16 MB

// ---------------------------------------------------------------------------
// Generic tiled SGEMM:
//   TRANSB=true : C[m,n] = scale * ( sum_k A[m,k]*B[n,k] + bias[n] )
//   TRANSB=false: C[m,n] = scale * ( sum_k A[m,k]*B[k,n] + bias[n] )
// Batched via blockIdx.z with two-level strides: off = (z/HN)*s0 + (z%HN)*s1
// ---------------------------------------------------------------------------
template<int BM, int BN, int BK, int TM, int TN, bool TRANSB>
__global__ void gemm_k(const float* __restrict__ A, const float* __restrict__ Bm,
                       const float* __restrict__ bias, float* __restrict__ C,
                       int M, int N, int K,
                       int lda, int ldb, int ldc,
                       long sA0, long sA1, long sB0, long sB1, long sC0, long sC1,
                       int HN, float scale)
{
    constexpr int THREADS = (BM / TM) * (BN / TN);
    __shared__ float As[BK][BM + 4];
    __shared__ float Bs[BK][BN + 4];

    const int z = blockIdx.z;
    const float* Ab = A  + (long)(z / HN) * sA0 + (long)(z % HN) * sA1;
    const float* Bb = Bm + (long)(z / HN) * sB0 + (long)(z % HN) * sB1;
    float*       Cb = C  + (long)(z / HN) * sC0 + (long)(z % HN) * sC1;

    const int m0  = blockIdx.y * BM;
    const int n0  = blockIdx.x * BN;
    const int tid = threadIdx.x;
    const int tx  = tid % (BN / TN);
    const int ty  = tid / (BN / TN);

    float acc[TM][TN];
#pragma unroll
    for (int i = 0; i < TM; i++)
#pragma unroll
        for (int j = 0; j < TN; j++) acc[i][j] = 0.f;

    for (int kt = 0; kt < K; kt += BK) {
        // A tile: BM x BK -> As[k][m] (transposed store)
        for (int idx = tid; idx < BM * BK / 4; idx += THREADS) {
            int row = idx / (BK / 4);
            int c4  = idx % (BK / 4);
            float4 v = *(const float4*)&Ab[(long)(m0 + row) * lda + kt + c4 * 4];
            As[c4 * 4 + 0][row] = v.x; As[c4 * 4 + 1][row] = v.y;
            As[c4 * 4 + 2][row] = v.z; As[c4 * 4 + 3][row] = v.w;
        }
        // B tile
        if (TRANSB) {
            for (int idx = tid; idx < BN * BK / 4; idx += THREADS) {
                int row = idx / (BK / 4);
                int c4  = idx % (BK / 4);
                float4 v = *(const float4*)&Bb[(long)(n0 + row) * ldb + kt + c4 * 4];
                Bs[c4 * 4 + 0][row] = v.x; Bs[c4 * 4 + 1][row] = v.y;
                Bs[c4 * 4 + 2][row] = v.z; Bs[c4 * 4 + 3][row] = v.w;
            }
        } else {
            for (int idx = tid; idx < BK * BN / 4; idx += THREADS) {
                int kk = idx / (BN / 4);
                int n4 = idx % (BN / 4);
                float4 v = *(const float4*)&Bb[(long)(kt + kk) * ldb + n0 + n4 * 4];
                *(float4*)&Bs[kk][n4 * 4] = v;
            }
        }
        __syncthreads();

#pragma unroll
        for (int k = 0; k < BK; k++) {
            float a[TM], b[TN];
#pragma unroll
            for (int i = 0; i < TM; i++) a[i] = As[k][ty * TM + i];
#pragma unroll
            for (int j = 0; j < TN; j++) b[j] = Bs[k][tx * TN + j];
#pragma unroll
            for (int i = 0; i < TM; i++)
#pragma unroll
                for (int j = 0; j < TN; j++)
                    acc[i][j] = fmaf(a[i], b[j], acc[i][j]);
        }
        __syncthreads();
    }

#pragma unroll
    for (int i = 0; i < TM; i++) {
        int m = m0 + ty * TM + i;
#pragma unroll
        for (int j = 0; j < TN; j++) {
            int n = n0 + tx * TN + j;
            float v = acc[i][j];
            if (bias) v += bias[n];
            Cb[(long)m * ldc + n] = v * scale;
        }
    }
}

// ---------------------------------------------------------------------------
// Row softmax over 1024-wide rows (in place). One block (256 thr) per row.
// ---------------------------------------------------------------------------
__global__ void softmax_rows(float* __restrict__ S)
{
    __shared__ float red[8];
    __shared__ float bcast;
    const long row = blockIdx.x;
    float* p = S + row * (long)LKV;
    const int tid = threadIdx.x;

    float4 v = *(float4*)&p[tid * 4];
    float m = fmaxf(fmaxf(v.x, v.y), fmaxf(v.z, v.w));
#pragma unroll
    for (int o = 16; o; o >>= 1) m = fmaxf(m, __shfl_xor_sync(0xffffffffu, m, o));
    if ((tid & 31) == 0) red[tid >> 5] = m;
    __syncthreads();
    if (tid < 8) {
        m = red[tid];
#pragma unroll
        for (int o = 4; o; o >>= 1) m = fmaxf(m, __shfl_xor_sync(0xffu, m, o));
        if (tid == 0) bcast = m;
    }
    __syncthreads();
    m = bcast;

    v.x = __expf(v.x - m); v.y = __expf(v.y - m);
    v.z = __expf(v.z - m); v.w = __expf(v.w - m);
    float s = (v.x + v.y) + (v.z + v.w);
#pragma unroll
    for (int o = 16; o; o >>= 1) s += __shfl_xor_sync(0xffffffffu, s, o);
    __syncthreads();  // everyone is done reading bcast/red
    if ((tid & 31) == 0) red[tid >> 5] = s;
    __syncthreads();
    if (tid < 8) {
        s = red[tid];
#pragma unroll
        for (int o = 4; o; o >>= 1) s += __shfl_xor_sync(0xffu, s, o);
        if (tid == 0) bcast = s;
    }
    __syncthreads();
    float inv = 1.0f / bcast;

    v.x *= inv; v.y *= inv; v.z *= inv; v.w *= inv;
    *(float4*)&p[tid * 4] = v;
}

// ---------------------------------------------------------------------------
// attn_weights = mean over heads of P.  P: [B,H,Lq,Lkv], out: [B,Lq,Lkv]
// ---------------------------------------------------------------------------
__global__ void mean_heads(const float* __restrict__ P, float* __restrict__ out)
{
    const long plane4 = (long)LQ * LKV / 4;   // 131072 float4 per (b,h) plane
    const int b = blockIdx.y;
    const long off = (long)blockIdx.x * blockDim.x + threadIdx.x;
    const float4* base = (const float4*)P + (long)b * HH_ * plane4 + off;
    float4 s = make_float4(0.f, 0.f, 0.f, 0.f);
#pragma unroll
    for (int h = 0; h < HH_; h++) {
        float4 v = base[(long)h * plane4];
        s.x += v.x; s.y += v.y; s.z += v.z; s.w += v.w;
    }
    const float inv = 1.0f / HH_;
    s.x *= inv; s.y *= inv; s.z *= inv; s.w *= inv;
    ((float4*)out)[(long)b * plane4 + off] = s;
}

// ---------------------------------------------------------------------------
// out = LayerNorm(query + attn_out) * gamma + beta.  One block per row (D=1024).
// ---------------------------------------------------------------------------
__global__ void residual_ln(const float* __restrict__ q, const float* __restrict__ ao,
                            const float* __restrict__ gamma, const float* __restrict__ beta,
                            float* __restrict__ out)
{
    __shared__ float red[8];
    __shared__ float bcast;
    const long row = blockIdx.x;
    const int tid = threadIdx.x;

    float4 qa = *(const float4*)&q [row * DD + tid * 4];
    float4 aa = *(const float4*)&ao[row * DD + tid * 4];
    float x0 = qa.x + aa.x, x1 = qa.y + aa.y, x2 = qa.z + aa.z, x3 = qa.w + aa.w;

    // mean
    float s = (x0 + x1) + (x2 + x3);
#pragma unroll
    for (int o = 16; o; o >>= 1) s += __shfl_xor_sync(0xffffffffu, s, o);
    if ((tid & 31) == 0) red[tid >> 5] = s;
    __syncthreads();
    if (tid < 8) {
        s = red[tid];
#pragma unroll
        for (int o = 4; o; o >>= 1) s += __shfl_xor_sync(0xffu, s, o);
        if (tid == 0) bcast = s;
    }
    __syncthreads();
    const float mu = bcast * (1.0f / DD);

    // variance
    float d0 = x0 - mu, d1 = x1 - mu, d2 = x2 - mu, d3 = x3 - mu;
    float sq = (d0 * d0 + d1 * d1) + (d2 * d2 + d3 * d3);
#pragma unroll
    for (int o = 16; o; o >>= 1) sq += __shfl_xor_sync(0xffffffffu, sq, o);
    __syncthreads();
    if ((tid & 31) == 0) red[tid >> 5] = sq;
    __syncthreads();
    if (tid < 8) {
        sq = red[tid];
#pragma unroll
        for (int o = 4; o; o >>= 1) sq += __shfl_xor_sync(0xffu, sq, o);
        if (tid == 0) bcast = sq;
    }
    __syncthreads();
    const float rstd = rsqrtf(bcast * (1.0f / DD) + LN_EPS);

    float4 g = *(const float4*)&gamma[tid * 4];
    float4 be = *(const float4*)&beta[tid * 4];
    float4 o4;
    o4.x = d0 * rstd * g.x + be.x;
    o4.y = d1 * rstd * g.y + be.y;
    o4.z = d2 * rstd * g.z + be.z;
    o4.w = d3 * rstd * g.w + be.w;
    *(float4*)&out[row * DD + tid * 4] = o4;
}

// ---------------------------------------------------------------------------
extern "C" void kernel_launch(void* const* d_in, const int* in_sizes, int n_in,
                              void* d_out, int out_size)
{
    const float* query = (const float*)d_in[0];
    const float* key_  = (const float*)d_in[1];
    const float* value = (const float*)d_in[2];
    const float* in_w  = (const float*)d_in[3];   // [3D, D]
    const float* in_b  = (const float*)d_in[4];   // [3D]
    const float* out_w = (const float*)d_in[5];   // [D, D]
    const float* out_b = (const float*)d_in[6];   // [D]
    const float* gamma = (const float*)d_in[7];
    const float* beta  = (const float*)d_in[8];
    float* out = (float*)d_out;

    float *Q, *K, *V, *S, *CTX, *AO;
    cudaGetSymbolAddress((void**)&Q,   g_Q);
    cudaGetSymbolAddress((void**)&K,   g_K);
    cudaGetSymbolAddress((void**)&V,   g_V);
    cudaGetSymbolAddress((void**)&S,   g_S);
    cudaGetSymbolAddress((void**)&CTX, g_CTX);
    cudaGetSymbolAddress((void**)&AO,  g_AO);

    const float qscale = 0.125f;  // 1/sqrt(hd)

    // Q projection: [4096,1024] = query @ wq^T, scaled (bias inside scale)
    gemm_k<128,128,8,8,8,true><<<dim3(DD/128, (BB*LQ)/128, 1), 256>>>(
        query, in_w, in_b, Q,
        BB*LQ, DD, DD, DD, DD, DD,
        0,0, 0,0, 0,0, 1, qscale);

    // K projection: [8192,1024]
    gemm_k<128,128,8,8,8,true><<<dim3(DD/128, (BB*LKV)/128, 1), 256>>>(
        key_, in_w + (long)DD*DD, in_b + DD, K,
        BB*LKV, DD, DD, DD, DD, DD,
        0,0, 0,0, 0,0, 1, 1.0f);

    // V projection: [8192,1024]
    gemm_k<128,128,8,8,8,true><<<dim3(DD/128, (BB*LKV)/128, 1), 256>>>(
        value, in_w + 2L*DD*DD, in_b + 2*DD, V,
        BB*LKV, DD, DD, DD, DD, DD,
        0,0, 0,0, 0,0, 1, 1.0f);

    // Scores: per (b,h)  S[512,1024] = Qh[512,64] @ Kh[1024,64]^T
    gemm_k<64,64,16,4,4,true><<<dim3(LKV/64, LQ/64, BB*HH_), 256>>>(
        Q, K, nullptr, S,
        LQ, LKV, HD, DD, DD, LKV,
        (long)LQ*DD, HD,                    // A strides (b, h)
        (long)LKV*DD, HD,                   // B strides (b, h)
        (long)HH_*LQ*LKV, (long)LQ*LKV,     // C strides (b, h)
        HH_, 1.0f);

    // Softmax in place over 64K rows
    softmax_rows<<<BB*HH_*LQ, 256>>>(S);

    // attn_weights = mean over heads -> second half of d_out
    mean_heads<<<dim3((LQ*LKV/4)/256, BB), 256>>>(S, out + (long)BB*LQ*DD);

    // ctx: per (b,h)  ctx[512,64] = P[512,1024] @ Vh[1024,64]  (written in [B,Lq,D] layout)
    gemm_k<64,64,16,4,4,false><<<dim3(1, LQ/64, BB*HH_), 256>>>(
        S, V, nullptr, CTX,
        LQ, HD, LKV, LKV, DD, DD,
        (long)HH_*LQ*LKV, (long)LQ*LKV,     // A strides (b, h)
        (long)LKV*DD, HD,                   // B strides (b, h)
        (long)LQ*DD, HD,                    // C strides (b, h)
        HH_, 1.0f);

    // Out projection
    gemm_k<128,128,8,8,8,true><<<dim3(DD/128, (BB*LQ)/128, 1), 256>>>(
        CTX, out_w, out_b, AO,
        BB*LQ, DD, DD, DD, DD, DD,
        0,0, 0,0, 0,0, 1, 1.0f);

    // Residual + LayerNorm -> first half of d_out
    residual_ln<<<BB*LQ, 256>>>(query, AO, gamma, beta, out);
}

// round 3
// speedup vs baseline: 1.7061x; 1.7061x over previous
#include <cuda_runtime.h>
#include <cuda_bf16.h>
#include <math.h>
#include <stdint.h>

// Problem constants
#define BB   8
#define LQ   512
#define LKV  1024
#define DD   1024
#define HH_  16
#define HD   64
#define LN_EPS 1e-5f

// ---------------------------------------------------------------------------
// Scratch (device globals: allocation-free per harness rules)
// ---------------------------------------------------------------------------
__device__ float g_Q  [BB * LQ  * DD];               // 16 MB  (pre-scaled q proj)
__device__ float g_K  [BB * LKV * DD];               // 32 MB
__device__ float g_V  [BB * LKV * DD];               // 32 MB
__device__ float g_S  [(size_t)BB * HH_ * LQ * LKV]; // 256 MB (scores -> probs)
__device__ float g_CTX[BB * LQ  * DD];               // 16 MB
__device__ float g_AO [BB * LQ  * DD];               // 16 MB

// bf16 hi/lo split buffers for tensor-core GEMMs
__device__ __align__(16) __nv_bfloat16 g_qh [BB * LQ  * DD], g_ql [BB * LQ  * DD];
__device__ __align__(16) __nv_bfloat16 g_kh [BB * LKV * DD], g_kl [BB * LKV * DD];
__device__ __align__(16) __nv_bfloat16 g_vh [BB * LKV * DD], g_vl [BB * LKV * DD];
__device__ __align__(16) __nv_bfloat16 g_wh [3 * DD * DD],   g_wl [3 * DD * DD];
__device__ __align__(16) __nv_bfloat16 g_woh[DD * DD],       g_wol[DD * DD];
__device__ __align__(16) __nv_bfloat16 g_ch [BB * LQ  * DD], g_cl [BB * LQ  * DD];

// ---------------------------------------------------------------------------
// Baseline-PTX tensor-core helpers (NO tcgen05 — compute_103 target!)
// ---------------------------------------------------------------------------
__device__ __forceinline__ uint32_t smem_u32(const void* p) {
    uint32_t a;
    asm("{ .reg .u64 t; cvta.to.shared.u64 t, %1; cvt.u32.u64 %0, t; }" : "=r"(a) : "l"(p));
    return a;
}
__device__ __forceinline__ void ldsm4(uint32_t& r0, uint32_t& r1, uint32_t& r2,
                                      uint32_t& r3, uint32_t a) {
    asm volatile("ldmatrix.sync.aligned.m8n8.x4.shared.b16 {%0,%1,%2,%3}, [%4];"
                 : "=r"(r0), "=r"(r1), "=r"(r2), "=r"(r3) : "r"(a));
}
__device__ __forceinline__ void mma_bf16(float* d, const uint32_t* a, const uint32_t* b) {
    asm volatile("mma.sync.aligned.m16n8k16.row.col.f32.bf16.bf16.f32 "
                 "{%0,%1,%2,%3},{%4,%5,%6,%7},{%8,%9},{%0,%1,%2,%3};"
                 : "+f"(d[0]), "+f"(d[1]), "+f"(d[2]), "+f"(d[3])
                 : "r"(a[0]), "r"(a[1]), "r"(a[2]), "r"(a[3]), "r"(b[0]), "r"(b[1]));
}
#define CP_ASYNC16(s, g) \
    asm volatile("cp.async.cg.shared.global [%0], [%1], 16;" :: "r"(s), "l"(g))
#define CP_COMMIT() asm volatile("cp.async.commit_group;" ::: "memory")
#define CP_WAIT1()  asm volatile("cp.async.wait_group 1;"  ::: "memory")

// ---------------------------------------------------------------------------
// fp32 -> bf16 hi/lo split (bf16x3 scheme)
// ---------------------------------------------------------------------------
__global__ void split_bf16(const float4* __restrict__ x,
                           __nv_bfloat162* __restrict__ hi,
                           __nv_bfloat162* __restrict__ lo, int n4)
{
    int i = blockIdx.x * blockDim.x + threadIdx.x;
    if (i >= n4) return;
    float4 v = x[i];
    __nv_bfloat16 h0 = __float2bfloat16(v.x);
    __nv_bfloat16 h1 = __float2bfloat16(v.y);
    __nv_bfloat16 h2 = __float2bfloat16(v.z);
    __nv_bfloat16 h3 = __float2bfloat16(v.w);
    __nv_bfloat16 l0 = __float2bfloat16(v.x - __bfloat162float(h0));
    __nv_bfloat16 l1 = __float2bfloat16(v.y - __bfloat162float(h1));
    __nv_bfloat16 l2 = __float2bfloat16(v.z - __bfloat162float(h2));
    __nv_bfloat16 l3 = __float2bfloat16(v.w - __bfloat162float(h3));
    hi[i * 2 + 0] = __halves2bfloat162(h0, h1);
    hi[i * 2 + 1] = __halves2bfloat162(h2, h3);
    lo[i * 2 + 0] = __halves2bfloat162(l0, l1);
    lo[i * 2 + 1] = __halves2bfloat162(l2, l3);
}

// ---------------------------------------------------------------------------
// HMMA bf16x3 GEMM:  C[M,1024] = scale * (Afp32 @ Bfp32^T + bias)
// A ~ Ahi+Alo [M,1024], B ~ Bhi+Blo [1024,1024], both K-major (lda/ldb = 1024).
// Block 128x128, BK=32, 8 warps (2x4), 3-stage cp.async pipeline.
// 96 K-iterations = 3 parts (hi*hi, hi*lo, lo*hi) x 32 chunks.
// ---------------------------------------------------------------------------
__global__ void __launch_bounds__(256) gemm_mma(
    const __nv_bfloat16* __restrict__ Ahi, const __nv_bfloat16* __restrict__ Alo,
    const __nv_bfloat16* __restrict__ Bhi, const __nv_bfloat16* __restrict__ Blo,
    const float* __restrict__ bias, float* __restrict__ C, float scale)
{
    __shared__ __align__(16) __nv_bfloat16 smA[3][128 * 32];
    __shared__ __align__(16) __nv_bfloat16 smB[3][128 * 32];

    const int tid  = threadIdx.x;
    const int lane = tid & 31;
    const int wid  = tid >> 5;
    const int wr   = wid >> 2;   // 0..1  (M direction, 64 rows each)
    const int wc   = wid & 3;    // 0..3  (N direction, 32 cols each)
    const int m0   = blockIdx.y * 128;
    const int n0   = blockIdx.x * 128;

    const uint32_t aS = smem_u32(smA);
    const uint32_t bS = smem_u32(smB);

    // per-thread cp.async mapping: 2 A-chunks + 2 B-chunks of 16B each
    // chunk q in [0,512): row r = q>>2, 16B col c = q&3; swizzle c ^= (r>>1)&3
    const int q0 = tid * 2;
    const int r0l = q0 >> 2,        c0l = q0 & 3;
    const int r1l = (q0 + 1) >> 2,  c1l = (q0 + 1) & 3;
    const uint32_t so0 = (uint32_t)(r0l * 64 + ((c0l ^ ((r0l >> 1) & 3)) << 4));
    const uint32_t so1 = (uint32_t)(r1l * 64 + ((c1l ^ ((r1l >> 1) & 3)) << 4));

    // ldmatrix lane mappings
    const int rA  = lane & 15;                       // row within 16-row tile
    const int cAh = lane >> 4;                       // k-half (0/1)
    const int rBl = (lane & 7) + ((lane & 16) >> 1); // row within 16-n tile
    const int cBh = (lane >> 3) & 1;                 // k-half (0/1)

    float acc[4][4][4];
#pragma unroll
    for (int mt = 0; mt < 4; ++mt)
#pragma unroll
        for (int nt = 0; nt < 4; ++nt)
#pragma unroll
            for (int j = 0; j < 4; ++j) acc[mt][nt][j] = 0.f;

    auto prefetch = [&](int it, int stage) {
        const int part = it >> 5;
        const int ko   = (it & 31) << 5;
        const __nv_bfloat16* Ap = (part == 2) ? Alo : Ahi;
        const __nv_bfloat16* Bp = (part == 1) ? Blo : Bhi;
        const uint32_t as = aS + stage * 8192u;
        const uint32_t bs = bS + stage * 8192u;
        CP_ASYNC16(as + so0, Ap + (((size_t)(m0 + r0l)) << 10) + ko + c0l * 8);
        CP_ASYNC16(as + so1, Ap + (((size_t)(m0 + r1l)) << 10) + ko + c1l * 8);
        CP_ASYNC16(bs + so0, Bp + (((size_t)(n0 + r0l)) << 10) + ko + c0l * 8);
        CP_ASYNC16(bs + so1, Bp + (((size_t)(n0 + r1l)) << 10) + ko + c1l * 8);
        CP_COMMIT();
    };

    const int NIT = 96;
    prefetch(0, 0);
    prefetch(1, 1);

    for (int it = 0; it < NIT; ++it) {
        CP_WAIT1();
        __syncthreads();
        if (it + 2 < NIT) prefetch(it + 2, (it + 2) % 3);
        else CP_COMMIT();   // keep group accounting uniform

        const uint32_t aT = aS + (uint32_t)(it % 3) * 8192u;
        const uint32_t bT = bS + (uint32_t)(it % 3) * 8192u;

#pragma unroll
        for (int ks = 0; ks < 2; ++ks) {
            uint32_t af[4][4];
            uint32_t bf[4][2];
#pragma unroll
            for (int mt = 0; mt < 4; ++mt) {
                int r = wr * 64 + mt * 16 + rA;
                int c = ks * 2 + cAh;
                ldsm4(af[mt][0], af[mt][1], af[mt][2], af[mt][3],
                      aT + (uint32_t)(r * 64 + ((c ^ ((r >> 1) & 3)) << 4)));
            }
#pragma unroll
            for (int tp = 0; tp < 2; ++tp) {
                int r = wc * 32 + tp * 16 + rBl;
                int c = ks * 2 + cBh;
                uint32_t x0, x1, x2, x3;
                ldsm4(x0, x1, x2, x3,
                      bT + (uint32_t)(r * 64 + ((c ^ ((r >> 1) & 3)) << 4)));
                bf[tp * 2][0] = x0;     bf[tp * 2][1] = x1;
                bf[tp * 2 + 1][0] = x2; bf[tp * 2 + 1][1] = x3;
            }
#pragma unroll
            for (int mt = 0; mt < 4; ++mt)
#pragma unroll
                for (int nt = 0; nt < 4; ++nt)
                    mma_bf16(acc[mt][nt], af[mt], bf[nt]);
        }
        __syncthreads();
    }

    // Epilogue: (acc + bias) * scale
#pragma unroll
    for (int mt = 0; mt < 4; ++mt) {
        const int row = m0 + wr * 64 + mt * 16 + (lane >> 2);
#pragma unroll
        for (int nt = 0; nt < 4; ++nt) {
            const int col = n0 + wc * 32 + nt * 8 + (lane & 3) * 2;
            const float b0 = bias[col], b1 = bias[col + 1];
            float* p0 = C + ((size_t)row << 10) + col;
            p0[0] = (acc[mt][nt][0] + b0) * scale;
            p0[1] = (acc[mt][nt][1] + b1) * scale;
            float* p1 = p0 + (8 << 10);
            p1[0] = (acc[mt][nt][2] + b0) * scale;
            p1[1] = (acc[mt][nt][3] + b1) * scale;
        }
    }
}

// ---------------------------------------------------------------------------
// fp32 tiled SGEMM (batched attention GEMMs this round)
// ---------------------------------------------------------------------------
template<int BM, int BN, int BK, int TM, int TN, bool TRANSB>
__global__ void gemm_k(const float* __restrict__ A, const float* __restrict__ Bm,
                       const float* __restrict__ bias, float* __restrict__ C,
                       int M, int N, int K,
                       int lda, int ldb, int ldc,
                       long sA0, long sA1, long sB0, long sB1, long sC0, long sC1,
                       int HN, float scale)
{
    constexpr int THREADS = (BM / TM) * (BN / TN);
    __shared__ float As[BK][BM + 4];
    __shared__ float Bs[BK][BN + 4];

    const int z = blockIdx.z;
    const float* Ab = A  + (long)(z / HN) * sA0 + (long)(z % HN) * sA1;
    const float* Bb = Bm + (long)(z / HN) * sB0 + (long)(z % HN) * sB1;
    float*       Cb = C  + (long)(z / HN) * sC0 + (long)(z % HN) * sC1;

    const int m0  = blockIdx.y * BM;
    const int n0  = blockIdx.x * BN;
    const int tid = threadIdx.x;
    const int tx  = tid % (BN / TN);
    const int ty  = tid / (BN / TN);

    float acc[TM][TN];
#pragma unroll
    for (int i = 0; i < TM; i++)
#pragma unroll
        for (int j = 0; j < TN; j++) acc[i][j] = 0.f;

    for (int kt = 0; kt < K; kt += BK) {
        for (int idx = tid; idx < BM * BK / 4; idx += THREADS) {
            int row = idx / (BK / 4);
            int c4  = idx % (BK / 4);
            float4 v = *(const float4*)&Ab[(long)(m0 + row) * lda + kt + c4 * 4];
            As[c4 * 4 + 0][row] = v.x; As[c4 * 4 + 1][row] = v.y;
            As[c4 * 4 + 2][row] = v.z; As[c4 * 4 + 3][row] = v.w;
        }
        if (TRANSB) {
            for (int idx = tid; idx < BN * BK / 4; idx += THREADS) {
                int row = idx / (BK / 4);
                int c4  = idx % (BK / 4);
                float4 v = *(const float4*)&Bb[(long)(n0 + row) * ldb + kt + c4 * 4];
                Bs[c4 * 4 + 0][row] = v.x; Bs[c4 * 4 + 1][row] = v.y;
                Bs[c4 * 4 + 2][row] = v.z; Bs[c4 * 4 + 3][row] = v.w;
            }
        } else {
            for (int idx = tid; idx < BK * BN / 4; idx += THREADS) {
                int kk = idx / (BN / 4);
                int n4 = idx % (BN / 4);
                float4 v = *(const float4*)&Bb[(long)(kt + kk) * ldb + n0 + n4 * 4];
                *(float4*)&Bs[kk][n4 * 4] = v;
            }
        }
        __syncthreads();

#pragma unroll
        for (int k = 0; k < BK; k++) {
            float a[TM], b[TN];
#pragma unroll
            for (int i = 0; i < TM; i++) a[i] = As[k][ty * TM + i];
#pragma unroll
            for (int j = 0; j < TN; j++) b[j] = Bs[k][tx * TN + j];
#pragma unroll
            for (int i = 0; i < TM; i++)
#pragma unroll
                for (int j = 0; j < TN; j++)
                    acc[i][j] = fmaf(a[i], b[j], acc[i][j]);
        }
        __syncthreads();
    }

#pragma unroll
    for (int i = 0; i < TM; i++) {
        int m = m0 + ty * TM + i;
#pragma unroll
        for (int j = 0; j < TN; j++) {
            int n = n0 + tx * TN + j;
            float v = acc[i][j];
            if (bias) v += bias[n];
            Cb[(long)m * ldc + n] = v * scale;
        }
    }
}

// ---------------------------------------------------------------------------
// Row softmax over 1024-wide rows (in place). One block (256 thr) per row.
// ---------------------------------------------------------------------------
__global__ void softmax_rows(float* __restrict__ S)
{
    __shared__ float red[8];
    __shared__ float bcast;
    const long row = blockIdx.x;
    float* p = S + row * (long)LKV;
    const int tid = threadIdx.x;

    float4 v = *(float4*)&p[tid * 4];
    float m = fmaxf(fmaxf(v.x, v.y), fmaxf(v.z, v.w));
#pragma unroll
    for (int o = 16; o; o >>= 1) m = fmaxf(m, __shfl_xor_sync(0xffffffffu, m, o));
    if ((tid & 31) == 0) red[tid >> 5] = m;
    __syncthreads();
    if (tid < 8) {
        m = red[tid];
#pragma unroll
        for (int o = 4; o; o >>= 1) m = fmaxf(m, __shfl_xor_sync(0xffu, m, o));
        if (tid == 0) bcast = m;
    }
    __syncthreads();
    m = bcast;

    v.x = __expf(v.x - m); v.y = __expf(v.y - m);
    v.z = __expf(v.z - m); v.w = __expf(v.w - m);
    float s = (v.x + v.y) + (v.z + v.w);
#pragma unroll
    for (int o = 16; o; o >>= 1) s += __shfl_xor_sync(0xffffffffu, s, o);
    __syncthreads();
    if ((tid & 31) == 0) red[tid >> 5] = s;
    __syncthreads();
    if (tid < 8) {
        s = red[tid];
#pragma unroll
        for (int o = 4; o; o >>= 1) s += __shfl_xor_sync(0xffu, s, o);
        if (tid == 0) bcast = s;
    }
    __syncthreads();
    float inv = 1.0f / bcast;

    v.x *= inv; v.y *= inv; v.z *= inv; v.w *= inv;
    *(float4*)&p[tid * 4] = v;
}

// ---------------------------------------------------------------------------
// attn_weights = mean over heads of P.  P: [B,H,Lq,Lkv], out: [B,Lq,Lkv]
// ---------------------------------------------------------------------------
__global__ void mean_heads(const float* __restrict__ P, float* __restrict__ out)
{
    const long plane4 = (long)LQ * LKV / 4;
    const int b = blockIdx.y;
    const long off = (long)blockIdx.x * blockDim.x + threadIdx.x;
    const float4* base = (const float4*)P + (long)b * HH_ * plane4 + off;
    float4 s = make_float4(0.f, 0.f, 0.f, 0.f);
#pragma unroll
    for (int h = 0; h < HH_; h++) {
        float4 v = base[(long)h * plane4];
        s.x += v.x; s.y += v.y; s.z += v.z; s.w += v.w;
    }
    const float inv = 1.0f / HH_;
    s.x *= inv; s.y *= inv; s.z *= inv; s.w *= inv;
    ((float4*)out)[(long)b * plane4 + off] = s;
}

// ---------------------------------------------------------------------------
// out = LayerNorm(query + attn_out) * gamma + beta.  One block per row.
// ---------------------------------------------------------------------------
__global__ void residual_ln(const float* __restrict__ q, const float* __restrict__ ao,
                            const float* __restrict__ gamma, const float* __restrict__ beta,
                            float* __restrict__ out)
{
    __shared__ float red[8];
    __shared__ float bcast;
    const long row = blockIdx.x;
    const int tid = threadIdx.x;

    float4 qa = *(const float4*)&q [row * DD + tid * 4];
    float4 aa = *(const float4*)&ao[row * DD + tid * 4];
    float x0 = qa.x + aa.x, x1 = qa.y + aa.y, x2 = qa.z + aa.z, x3 = qa.w + aa.w;

    float s = (x0 + x1) + (x2 + x3);
#pragma unroll
    for (int o = 16; o; o >>= 1) s += __shfl_xor_sync(0xffffffffu, s, o);
    if ((tid & 31) == 0) red[tid >> 5] = s;
    __syncthreads();
    if (tid < 8) {
        s = red[tid];
#pragma unroll
        for (int o = 4; o; o >>= 1) s += __shfl_xor_sync(0xffu, s, o);
        if (tid == 0) bcast = s;
    }
    __syncthreads();
    const float mu = bcast * (1.0f / DD);

    float d0 = x0 - mu, d1 = x1 - mu, d2 = x2 - mu, d3 = x3 - mu;
    float sq = (d0 * d0 + d1 * d1) + (d2 * d2 + d3 * d3);
#pragma unroll
    for (int o = 16; o; o >>= 1) sq += __shfl_xor_sync(0xffffffffu, sq, o);
    __syncthreads();
    if ((tid & 31) == 0) red[tid >> 5] = sq;
    __syncthreads();
    if (tid < 8) {
        sq = red[tid];
#pragma unroll
        for (int o = 4; o; o >>= 1) sq += __shfl_xor_sync(0xffu, sq, o);
        if (tid == 0) bcast = sq;
    }
    __syncthreads();
    const float rstd = rsqrtf(bcast * (1.0f / DD) + LN_EPS);

    float4 g = *(const float4*)&gamma[tid * 4];
    float4 be = *(const float4*)&beta[tid * 4];
    float4 o4;
    o4.x = d0 * rstd * g.x + be.x;
    o4.y = d1 * rstd * g.y + be.y;
    o4.z = d2 * rstd * g.z + be.z;
    o4.w = d3 * rstd * g.w + be.w;
    *(float4*)&out[row * DD + tid * 4] = o4;
}

// ---------------------------------------------------------------------------
extern "C" void kernel_launch(void* const* d_in, const int* in_sizes, int n_in,
                              void* d_out, int out_size)
{
    const float* query = (const float*)d_in[0];
    const float* key_  = (const float*)d_in[1];
    const float* value = (const float*)d_in[2];
    const float* in_w  = (const float*)d_in[3];   // [3D, D]
    const float* in_b  = (const float*)d_in[4];   // [3D]
    const float* out_w = (const float*)d_in[5];   // [D, D]
    const float* out_b = (const float*)d_in[6];   // [D]
    const float* gamma = (const float*)d_in[7];
    const float* beta  = (const float*)d_in[8];
    float* out = (float*)d_out;

    float *Q, *K, *V, *S, *CTX, *AO;
    cudaGetSymbolAddress((void**)&Q,   g_Q);
    cudaGetSymbolAddress((void**)&K,   g_K);
    cudaGetSymbolAddress((void**)&V,   g_V);
    cudaGetSymbolAddress((void**)&S,   g_S);
    cudaGetSymbolAddress((void**)&CTX, g_CTX);
    cudaGetSymbolAddress((void**)&AO,  g_AO);

    __nv_bfloat16 *qh, *ql, *kh, *kl, *vh, *vl, *wh, *wl, *woh, *wol, *ch, *cl;
    cudaGetSymbolAddress((void**)&qh,  g_qh);  cudaGetSymbolAddress((void**)&ql,  g_ql);
    cudaGetSymbolAddress((void**)&kh,  g_kh);  cudaGetSymbolAddress((void**)&kl,  g_kl);
    cudaGetSymbolAddress((void**)&vh,  g_vh);  cudaGetSymbolAddress((void**)&vl,  g_vl);
    cudaGetSymbolAddress((void**)&wh,  g_wh);  cudaGetSymbolAddress((void**)&wl,  g_wl);
    cudaGetSymbolAddress((void**)&woh, g_woh); cudaGetSymbolAddress((void**)&wol, g_wol);
    cudaGetSymbolAddress((void**)&ch,  g_ch);  cudaGetSymbolAddress((void**)&cl,  g_cl);

    const float qscale = 0.125f;  // 1/sqrt(hd)

    // Split fp32 inputs/weights into bf16 hi/lo
    auto launch_split = [](const float* x, __nv_bfloat16* h, __nv_bfloat16* l, long n) {
        int n4 = (int)(n / 4);
        split_bf16<<<(n4 + 255) / 256, 256>>>((const float4*)x, (__nv_bfloat162*)h,
                                              (__nv_bfloat162*)l, n4);
    };
    launch_split(query, qh, ql, (long)BB * LQ  * DD);
    launch_split(key_,  kh, kl, (long)BB * LKV * DD);
    launch_split(value, vh, vl, (long)BB * LKV * DD);
    launch_split(in_w,  wh, wl, 3L * DD * DD);
    launch_split(out_w, woh, wol, (long)DD * DD);

    // Q/K/V projections on HMMA tensor cores (bf16x3), fp32 outputs
    gemm_mma<<<dim3(DD / 128, (BB * LQ) / 128),  256>>>(
        qh, ql, wh,               wl,               in_b,        Q, qscale);
    gemm_mma<<<dim3(DD / 128, (BB * LKV) / 128), 256>>>(
        kh, kl, wh + (long)DD*DD, wl + (long)DD*DD, in_b + DD,   K, 1.0f);
    gemm_mma<<<dim3(DD / 128, (BB * LKV) / 128), 256>>>(
        vh, vl, wh + 2L*DD*DD,    wl + 2L*DD*DD,    in_b + 2*DD, V, 1.0f);

    // Scores: per (b,h)  S[512,1024] = Qh[512,64] @ Kh[1024,64]^T  (fp32)
    gemm_k<64,64,16,4,4,true><<<dim3(LKV/64, LQ/64, BB*HH_), 256>>>(
        Q, K, nullptr, S,
        LQ, LKV, HD, DD, DD, LKV,
        (long)LQ*DD, HD,
        (long)LKV*DD, HD,
        (long)HH_*LQ*LKV, (long)LQ*LKV,
        HH_, 1.0f);

    // Softmax in place over 64K rows
    softmax_rows<<<BB*HH_*LQ, 256>>>(S);

    // attn_weights = mean over heads -> second half of d_out
    mean_heads<<<dim3((LQ*LKV/4)/256, BB), 256>>>(S, out + (long)BB*LQ*DD);

    // ctx: per (b,h)  ctx[512,64] = P[512,1024] @ Vh[1024,64]  (fp32)
    gemm_k<64,64,16,4,4,false><<<dim3(1, LQ/64, BB*HH_), 256>>>(
        S, V, nullptr, CTX,
        LQ, HD, LKV, LKV, DD, DD,
        (long)HH_*LQ*LKV, (long)LQ*LKV,
        (long)LKV*DD, HD,
        (long)LQ*DD, HD,
        HH_, 1.0f);

    // Out projection on HMMA (bf16x3): split CTX, then GEMM
    launch_split(CTX, ch, cl, (long)BB * LQ * DD);
    gemm_mma<<<dim3(DD / 128, (BB * LQ) / 128), 256>>>(
        ch, cl, woh, wol, out_b, AO, 1.0f);

    // Residual + LayerNorm -> first half of d_out
    residual_ln<<<BB*LQ, 256>>>(query, AO, gamma, beta, out);
}

// round 4
// speedup vs baseline: 2.1509x; 1.2607x over previous
#include <cuda_runtime.h>
#include <cuda_bf16.h>
#include <math.h>
#include <stdint.h>

// Problem constants
#define BB   8
#define LQ   512
#define LKV  1024
#define DD   1024
#define HH_  16
#define HD   64
#define LN_EPS 1e-5f

// ---------------------------------------------------------------------------
// Scratch (device globals: allocation-free per harness rules)
// ---------------------------------------------------------------------------
__device__ float g_Q  [BB * LQ  * DD];               // fp32 q proj (pre-scaled)
__device__ float g_K  [BB * LKV * DD];
__device__ float g_V  [BB * LKV * DD];
__device__ float g_S  [(size_t)BB * HH_ * LQ * LKV]; // fp32 scores
__device__ float g_CTX[BB * LQ  * DD];
__device__ float g_AO [BB * LQ  * DD];

// bf16 hi/lo split buffers (REUSED: input splits, then projection splits)
__device__ __align__(16) __nv_bfloat16 g_qh [BB * LQ  * DD], g_ql [BB * LQ  * DD];
__device__ __align__(16) __nv_bfloat16 g_kh [BB * LKV * DD], g_kl [BB * LKV * DD];
__device__ __align__(16) __nv_bfloat16 g_vh [BB * LKV * DD], g_vl [BB * LKV * DD];
__device__ __align__(16) __nv_bfloat16 g_wh [3 * DD * DD],   g_wl [3 * DD * DD];
__device__ __align__(16) __nv_bfloat16 g_woh[DD * DD],       g_wol[DD * DD];
__device__ __align__(16) __nv_bfloat16 g_ch [BB * LQ  * DD], g_cl [BB * LQ  * DD];
// probs hi/lo [B,H,Lq,Lkv]
__device__ __align__(16) __nv_bfloat16 g_ph [(size_t)BB * HH_ * LQ * LKV];
__device__ __align__(16) __nv_bfloat16 g_pl [(size_t)BB * HH_ * LQ * LKV];

// ---------------------------------------------------------------------------
// Baseline-PTX tensor-core helpers (NO tcgen05 — compute_103 target!)
// ---------------------------------------------------------------------------
__device__ __forceinline__ uint32_t smem_u32(const void* p) {
    uint32_t a;
    asm("{ .reg .u64 t; cvta.to.shared.u64 t, %1; cvt.u32.u64 %0, t; }" : "=r"(a) : "l"(p));
    return a;
}
__device__ __forceinline__ void ldsm4(uint32_t& r0, uint32_t& r1, uint32_t& r2,
                                      uint32_t& r3, uint32_t a) {
    asm volatile("ldmatrix.sync.aligned.m8n8.x4.shared.b16 {%0,%1,%2,%3}, [%4];"
                 : "=r"(r0), "=r"(r1), "=r"(r2), "=r"(r3) : "r"(a));
}
__device__ __forceinline__ void mma_bf16(float* d, const uint32_t* a, const uint32_t* b) {
    asm volatile("mma.sync.aligned.m16n8k16.row.col.f32.bf16.bf16.f32 "
                 "{%0,%1,%2,%3},{%4,%5,%6,%7},{%8,%9},{%0,%1,%2,%3};"
                 : "+f"(d[0]), "+f"(d[1]), "+f"(d[2]), "+f"(d[3])
                 : "r"(a[0]), "r"(a[1]), "r"(a[2]), "r"(a[3]), "r"(b[0]), "r"(b[1]));
}
#define CP_ASYNC16(s, g) \
    asm volatile("cp.async.cg.shared.global [%0], [%1], 16;" :: "r"(s), "l"(g))
#define CP_COMMIT() asm volatile("cp.async.commit_group;" ::: "memory")
#define CP_WAIT1()  asm volatile("cp.async.wait_group 1;"  ::: "memory")

// ---------------------------------------------------------------------------
// fp32 -> bf16 hi/lo split (bf16x3 scheme)
// ---------------------------------------------------------------------------
__global__ void split_bf16(const float4* __restrict__ x,
                           __nv_bfloat162* __restrict__ hi,
                           __nv_bfloat162* __restrict__ lo, int n4)
{
    int i = blockIdx.x * blockDim.x + threadIdx.x;
    if (i >= n4) return;
    float4 v = x[i];
    __nv_bfloat16 h0 = __float2bfloat16(v.x);
    __nv_bfloat16 h1 = __float2bfloat16(v.y);
    __nv_bfloat16 h2 = __float2bfloat16(v.z);
    __nv_bfloat16 h3 = __float2bfloat16(v.w);
    __nv_bfloat16 l0 = __float2bfloat16(v.x - __bfloat162float(h0));
    __nv_bfloat16 l1 = __float2bfloat16(v.y - __bfloat162float(h1));
    __nv_bfloat16 l2 = __float2bfloat16(v.z - __bfloat162float(h2));
    __nv_bfloat16 l3 = __float2bfloat16(v.w - __bfloat162float(h3));
    hi[i * 2 + 0] = __halves2bfloat162(h0, h1);
    hi[i * 2 + 1] = __halves2bfloat162(h2, h3);
    lo[i * 2 + 0] = __halves2bfloat162(l0, l1);
    lo[i * 2 + 1] = __halves2bfloat162(l2, l3);
}

// ---------------------------------------------------------------------------
// Transpose + split V: fp32 V[b*Lkv + k][h*64 + n] -> Vt hi/lo [(b*16+h)*64 + n][k]
// ---------------------------------------------------------------------------
__global__ void transpose_split_v(const float* __restrict__ V,
                                  __nv_bfloat16* __restrict__ hi,
                                  __nv_bfloat16* __restrict__ lo)
{
    __shared__ float t[32][33];
    const int z = blockIdx.z, b = z >> 4, h = z & 15;
    const int k0 = blockIdx.x * 32, nn0 = blockIdx.y * 32;
    const int tx = threadIdx.x & 31, ty = threadIdx.x >> 5;   // ty 0..7
#pragma unroll
    for (int i = 0; i < 4; ++i) {
        int k = k0 + ty + i * 8;
        t[ty + i * 8][tx] = V[(((size_t)(b * 1024 + k)) << 10) + h * 64 + nn0 + tx];
    }
    __syncthreads();
#pragma unroll
    for (int i = 0; i < 4; ++i) {
        int n = nn0 + ty + i * 8;
        float v = t[tx][ty + i * 8];
        __nv_bfloat16 hh = __float2bfloat16(v);
        size_t o = (((size_t)(z * 64 + n)) << 10) + k0 + tx;
        hi[o] = hh;
        lo[o] = __float2bfloat16(v - __bfloat162float(hh));
    }
}

// ---------------------------------------------------------------------------
// HMMA bf16x3 GEMM:  C[M,1024] = scale * (Afp32 @ Bfp32^T + bias)
// Block 128x128, BK=32, 8 warps (2x4), 3-stage cp.async pipeline. NIT=96.
// ---------------------------------------------------------------------------
__global__ void __launch_bounds__(256) gemm_mma(
    const __nv_bfloat16* __restrict__ Ahi, const __nv_bfloat16* __restrict__ Alo,
    const __nv_bfloat16* __restrict__ Bhi, const __nv_bfloat16* __restrict__ Blo,
    const float* __restrict__ bias, float* __restrict__ C, float scale)
{
    __shared__ __align__(16) __nv_bfloat16 smA[3][128 * 32];
    __shared__ __align__(16) __nv_bfloat16 smB[3][128 * 32];

    const int tid  = threadIdx.x;
    const int lane = tid & 31;
    const int wid  = tid >> 5;
    const int wr   = wid >> 2;
    const int wc   = wid & 3;
    const int m0   = blockIdx.y * 128;
    const int n0   = blockIdx.x * 128;

    const uint32_t aS = smem_u32(smA);
    const uint32_t bS = smem_u32(smB);

    const int q0 = tid * 2;
    const int r0l = q0 >> 2,        c0l = q0 & 3;
    const int r1l = (q0 + 1) >> 2,  c1l = (q0 + 1) & 3;
    const uint32_t so0 = (uint32_t)(r0l * 64 + ((c0l ^ ((r0l >> 1) & 3)) << 4));
    const uint32_t so1 = (uint32_t)(r1l * 64 + ((c1l ^ ((r1l >> 1) & 3)) << 4));

    const int rA  = lane & 15;
    const int cAh = lane >> 4;
    const int rBl = (lane & 7) + ((lane & 16) >> 1);
    const int cBh = (lane >> 3) & 1;

    float acc[4][4][4];
#pragma unroll
    for (int mt = 0; mt < 4; ++mt)
#pragma unroll
        for (int nt = 0; nt < 4; ++nt)
#pragma unroll
            for (int j = 0; j < 4; ++j) acc[mt][nt][j] = 0.f;

    auto prefetch = [&](int it, int stage) {
        const int part = it >> 5;
        const int ko   = (it & 31) << 5;
        const __nv_bfloat16* Ap = (part == 2) ? Alo : Ahi;
        const __nv_bfloat16* Bp = (part == 1) ? Blo : Bhi;
        const uint32_t as = aS + stage * 8192u;
        const uint32_t bs = bS + stage * 8192u;
        CP_ASYNC16(as + so0, Ap + (((size_t)(m0 + r0l)) << 10) + ko + c0l * 8);
        CP_ASYNC16(as + so1, Ap + (((size_t)(m0 + r1l)) << 10) + ko + c1l * 8);
        CP_ASYNC16(bs + so0, Bp + (((size_t)(n0 + r0l)) << 10) + ko + c0l * 8);
        CP_ASYNC16(bs + so1, Bp + (((size_t)(n0 + r1l)) << 10) + ko + c1l * 8);
        CP_COMMIT();
    };

    const int NIT = 96;
    prefetch(0, 0);
    prefetch(1, 1);

    for (int it = 0; it < NIT; ++it) {
        CP_WAIT1();
        __syncthreads();
        if (it + 2 < NIT) prefetch(it + 2, (it + 2) % 3);
        else CP_COMMIT();

        const uint32_t aT = aS + (uint32_t)(it % 3) * 8192u;
        const uint32_t bT = bS + (uint32_t)(it % 3) * 8192u;

#pragma unroll
        for (int ks = 0; ks < 2; ++ks) {
            uint32_t af[4][4];
            uint32_t bf[4][2];
#pragma unroll
            for (int mt = 0; mt < 4; ++mt) {
                int r = wr * 64 + mt * 16 + rA;
                int c = ks * 2 + cAh;
                ldsm4(af[mt][0], af[mt][1], af[mt][2], af[mt][3],
                      aT + (uint32_t)(r * 64 + ((c ^ ((r >> 1) & 3)) << 4)));
            }
#pragma unroll
            for (int tp = 0; tp < 2; ++tp) {
                int r = wc * 32 + tp * 16 + rBl;
                int c = ks * 2 + cBh;
                uint32_t x0, x1, x2, x3;
                ldsm4(x0, x1, x2, x3,
                      bT + (uint32_t)(r * 64 + ((c ^ ((r >> 1) & 3)) << 4)));
                bf[tp * 2][0] = x0;     bf[tp * 2][1] = x1;
                bf[tp * 2 + 1][0] = x2; bf[tp * 2 + 1][1] = x3;
            }
#pragma unroll
            for (int mt = 0; mt < 4; ++mt)
#pragma unroll
                for (int nt = 0; nt < 4; ++nt)
                    mma_bf16(acc[mt][nt], af[mt], bf[nt]);
        }
        __syncthreads();
    }

#pragma unroll
    for (int mt = 0; mt < 4; ++mt) {
        const int row = m0 + wr * 64 + mt * 16 + (lane >> 2);
#pragma unroll
        for (int nt = 0; nt < 4; ++nt) {
            const int col = n0 + wc * 32 + nt * 8 + (lane & 3) * 2;
            const float b0 = bias[col], b1 = bias[col + 1];
            float* p0 = C + ((size_t)row << 10) + col;
            p0[0] = (acc[mt][nt][0] + b0) * scale;
            p0[1] = (acc[mt][nt][1] + b1) * scale;
            float* p1 = p0 + (8 << 10);
            p1[0] = (acc[mt][nt][2] + b0) * scale;
            p1[1] = (acc[mt][nt][3] + b1) * scale;
        }
    }
}

// ---------------------------------------------------------------------------
// HMMA bf16x3 batched scores: per z=(b,h)  S[512,1024] = Qh[512,64] @ Kh[1024,64]^T
// Same tiling as gemm_mma; K=64 per part -> NIT = 6. fp32 output, no bias.
// ---------------------------------------------------------------------------
__global__ void __launch_bounds__(256) scores_mma(
    const __nv_bfloat16* __restrict__ Qhi, const __nv_bfloat16* __restrict__ Qlo,
    const __nv_bfloat16* __restrict__ Khi, const __nv_bfloat16* __restrict__ Klo,
    float* __restrict__ S)
{
    __shared__ __align__(16) __nv_bfloat16 smA[3][128 * 32];
    __shared__ __align__(16) __nv_bfloat16 smB[3][128 * 32];

    const int tid  = threadIdx.x;
    const int lane = tid & 31;
    const int wid  = tid >> 5;
    const int wr   = wid >> 2;
    const int wc   = wid & 3;
    const int z    = blockIdx.z, b = z >> 4, h = z & 15;
    const int m0   = blockIdx.y * 128;
    const int n0   = blockIdx.x * 128;
    const size_t aOff = (((size_t)b * 512) << 10) + h * 64;
    const size_t bOff = (((size_t)b * 1024) << 10) + h * 64;

    const uint32_t aS = smem_u32(smA);
    const uint32_t bS = smem_u32(smB);

    const int q0 = tid * 2;
    const int r0l = q0 >> 2,        c0l = q0 & 3;
    const int r1l = (q0 + 1) >> 2,  c1l = (q0 + 1) & 3;
    const uint32_t so0 = (uint32_t)(r0l * 64 + ((c0l ^ ((r0l >> 1) & 3)) << 4));
    const uint32_t so1 = (uint32_t)(r1l * 64 + ((c1l ^ ((r1l >> 1) & 3)) << 4));

    const int rA  = lane & 15;
    const int cAh = lane >> 4;
    const int rBl = (lane & 7) + ((lane & 16) >> 1);
    const int cBh = (lane >> 3) & 1;

    float acc[4][4][4];
#pragma unroll
    for (int mt = 0; mt < 4; ++mt)
#pragma unroll
        for (int nt = 0; nt < 4; ++nt)
#pragma unroll
            for (int j = 0; j < 4; ++j) acc[mt][nt][j] = 0.f;

    auto prefetch = [&](int it, int stage) {
        const int part = it >> 1;            // 0,1,2
        const int ko   = (it & 1) << 5;      // 0,32
        const __nv_bfloat16* Ap = (part == 2) ? Qlo : Qhi;
        const __nv_bfloat16* Bp = (part == 1) ? Klo : Khi;
        const uint32_t as = aS + stage * 8192u;
        const uint32_t bs = bS + stage * 8192u;
        CP_ASYNC16(as + so0, Ap + aOff + (((size_t)(m0 + r0l)) << 10) + ko + c0l * 8);
        CP_ASYNC16(as + so1, Ap + aOff + (((size_t)(m0 + r1l)) << 10) + ko + c1l * 8);
        CP_ASYNC16(bs + so0, Bp + bOff + (((size_t)(n0 + r0l)) << 10) + ko + c0l * 8);
        CP_ASYNC16(bs + so1, Bp + bOff + (((size_t)(n0 + r1l)) << 10) + ko + c1l * 8);
        CP_COMMIT();
    };

    const int NIT = 6;
    prefetch(0, 0);
    prefetch(1, 1);

    for (int it = 0; it < NIT; ++it) {
        CP_WAIT1();
        __syncthreads();
        if (it + 2 < NIT) prefetch(it + 2, (it + 2) % 3);
        else CP_COMMIT();

        const uint32_t aT = aS + (uint32_t)(it % 3) * 8192u;
        const uint32_t bT = bS + (uint32_t)(it % 3) * 8192u;

#pragma unroll
        for (int ks = 0; ks < 2; ++ks) {
            uint32_t af[4][4];
            uint32_t bf[4][2];
#pragma unroll
            for (int mt = 0; mt < 4; ++mt) {
                int r = wr * 64 + mt * 16 + rA;
                int c = ks * 2 + cAh;
                ldsm4(af[mt][0], af[mt][1], af[mt][2], af[mt][3],
                      aT + (uint32_t)(r * 64 + ((c ^ ((r >> 1) & 3)) << 4)));
            }
#pragma unroll
            for (int tp = 0; tp < 2; ++tp) {
                int r = wc * 32 + tp * 16 + rBl;
                int c = ks * 2 + cBh;
                uint32_t x0, x1, x2, x3;
                ldsm4(x0, x1, x2, x3,
                      bT + (uint32_t)(r * 64 + ((c ^ ((r >> 1) & 3)) << 4)));
                bf[tp * 2][0] = x0;     bf[tp * 2][1] = x1;
                bf[tp * 2 + 1][0] = x2; bf[tp * 2 + 1][1] = x3;
            }
#pragma unroll
            for (int mt = 0; mt < 4; ++mt)
#pragma unroll
                for (int nt = 0; nt < 4; ++nt)
                    mma_bf16(acc[mt][nt], af[mt], bf[nt]);
        }
        __syncthreads();
    }

    float* Sb = S + (size_t)z * (512 * 1024);
#pragma unroll
    for (int mt = 0; mt < 4; ++mt) {
        const int row = m0 + wr * 64 + mt * 16 + (lane >> 2);
#pragma unroll
        for (int nt = 0; nt < 4; ++nt) {
            const int col = n0 + wc * 32 + nt * 8 + (lane & 3) * 2;
            float* p0 = Sb + ((size_t)row << 10) + col;
            p0[0] = acc[mt][nt][0];
            p0[1] = acc[mt][nt][1];
            float* p1 = p0 + (8 << 10);
            p1[0] = acc[mt][nt][2];
            p1[1] = acc[mt][nt][3];
        }
    }
}

// ---------------------------------------------------------------------------
// HMMA bf16x3 batched ctx: per z=(b,h)  ctx[512,64] = P[512,1024] @ Vt[64,1024]^T
// Block 128x64, 8 warps (2x4, warp tile 64x16), BK=32, NIT = 96. Writes into
// CTX at [b*512+m][h*64+n] (fp32).
// ---------------------------------------------------------------------------
__global__ void __launch_bounds__(256) ctx_mma(
    const __nv_bfloat16* __restrict__ Phi, const __nv_bfloat16* __restrict__ Plo,
    const __nv_bfloat16* __restrict__ Vhi, const __nv_bfloat16* __restrict__ Vlo,
    float* __restrict__ CTX)
{
    __shared__ __align__(16) __nv_bfloat16 smA[3][128 * 32];
    __shared__ __align__(16) __nv_bfloat16 smB[3][64 * 32];

    const int tid  = threadIdx.x;
    const int lane = tid & 31;
    const int wid  = tid >> 5;
    const int wr   = wid >> 2;   // 0..1 (64 rows)
    const int wc   = wid & 3;    // 0..3 (16 cols)
    const int z    = blockIdx.z, b = z >> 4, h = z & 15;
    const int m0   = blockIdx.y * 128;
    const size_t aOff = ((size_t)z * 512) << 10;
    const size_t bOff = ((size_t)z * 64) << 10;

    const uint32_t aS = smem_u32(smA);
    const uint32_t bS = smem_u32(smB);

    // A: 512 chunks of 16B, 2 per thread
    const int q0 = tid * 2;
    const int r0l = q0 >> 2,        c0l = q0 & 3;
    const int r1l = (q0 + 1) >> 2,  c1l = (q0 + 1) & 3;
    const uint32_t so0 = (uint32_t)(r0l * 64 + ((c0l ^ ((r0l >> 1) & 3)) << 4));
    const uint32_t so1 = (uint32_t)(r1l * 64 + ((c1l ^ ((r1l >> 1) & 3)) << 4));
    // B: 256 chunks of 16B, 1 per thread
    const int rb = tid >> 2, cb = tid & 3;
    const uint32_t sob = (uint32_t)(rb * 64 + ((cb ^ ((rb >> 1) & 3)) << 4));

    const int rA  = lane & 15;
    const int cAh = lane >> 4;
    const int rBl = (lane & 7) + ((lane & 16) >> 1);
    const int cBh = (lane >> 3) & 1;

    float acc[4][2][4];
#pragma unroll
    for (int mt = 0; mt < 4; ++mt)
#pragma unroll
        for (int nt = 0; nt < 2; ++nt)
#pragma unroll
            for (int j = 0; j < 4; ++j) acc[mt][nt][j] = 0.f;

    auto prefetch = [&](int it, int stage) {
        const int part = it >> 5;
        const int ko   = (it & 31) << 5;
        const __nv_bfloat16* Ap = (part == 2) ? Plo : Phi;
        const __nv_bfloat16* Bp = (part == 1) ? Vlo : Vhi;
        const uint32_t as = aS + stage * 8192u;
        const uint32_t bs = bS + stage * 4096u;
        CP_ASYNC16(as + so0, Ap + aOff + (((size_t)(m0 + r0l)) << 10) + ko + c0l * 8);
        CP_ASYNC16(as + so1, Ap + aOff + (((size_t)(m0 + r1l)) << 10) + ko + c1l * 8);
        CP_ASYNC16(bs + sob, Bp + bOff + (((size_t)rb) << 10) + ko + cb * 8);
        CP_COMMIT();
    };

    const int NIT = 96;
    prefetch(0, 0);
    prefetch(1, 1);

    for (int it = 0; it < NIT; ++it) {
        CP_WAIT1();
        __syncthreads();
        if (it + 2 < NIT) prefetch(it + 2, (it + 2) % 3);
        else CP_COMMIT();

        const uint32_t aT = aS + (uint32_t)(it % 3) * 8192u;
        const uint32_t bT = bS + (uint32_t)(it % 3) * 4096u;

#pragma unroll
        for (int ks = 0; ks < 2; ++ks) {
            uint32_t af[4][4];
            uint32_t bf[2][2];
#pragma unroll
            for (int mt = 0; mt < 4; ++mt) {
                int r = wr * 64 + mt * 16 + rA;
                int c = ks * 2 + cAh;
                ldsm4(af[mt][0], af[mt][1], af[mt][2], af[mt][3],
                      aT + (uint32_t)(r * 64 + ((c ^ ((r >> 1) & 3)) << 4)));
            }
            {
                int r = wc * 16 + rBl;
                int c = ks * 2 + cBh;
                uint32_t x0, x1, x2, x3;
                ldsm4(x0, x1, x2, x3,
                      bT + (uint32_t)(r * 64 + ((c ^ ((r >> 1) & 3)) << 4)));
                bf[0][0] = x0; bf[0][1] = x1;
                bf[1][0] = x2; bf[1][1] = x3;
            }
#pragma unroll
            for (int mt = 0; mt < 4; ++mt)
#pragma unroll
                for (int nt = 0; nt < 2; ++nt)
                    mma_bf16(acc[mt][nt], af[mt], bf[nt]);
        }
        __syncthreads();
    }

#pragma unroll
    for (int mt = 0; mt < 4; ++mt) {
        const int row = m0 + wr * 64 + mt * 16 + (lane >> 2);
#pragma unroll
        for (int nt = 0; nt < 2; ++nt) {
            const int col = wc * 16 + nt * 8 + (lane & 3) * 2;
            float* p0 = CTX + (((size_t)(b * 512 + row)) << 10) + h * 64 + col;
            p0[0] = acc[mt][nt][0];
            p0[1] = acc[mt][nt][1];
            float* p1 = p0 + (8 << 10);
            p1[0] = acc[mt][nt][2];
            p1[1] = acc[mt][nt][3];
        }
    }
}

// ---------------------------------------------------------------------------
// Fused softmax + head-mean. One block per (b,q); loops over 16 heads.
// Emits probs as bf16 hi/lo and attn_weights mean directly.
// ---------------------------------------------------------------------------
__global__ void softmax_meanheads(const float* __restrict__ S,
                                  __nv_bfloat162* __restrict__ ph,
                                  __nv_bfloat162* __restrict__ pl,
                                  float* __restrict__ mean_out)
{
    __shared__ float red[8];
    __shared__ float bcast;
    const int bq = blockIdx.x;           // b*512 + q
    const int b = bq >> 9, q = bq & 511;
    const int tid = threadIdx.x;

    float4 macc = make_float4(0.f, 0.f, 0.f, 0.f);

#pragma unroll 1
    for (int h = 0; h < HH_; ++h) {
        const size_t rowe = ((size_t)(b * 16 + h) * 512 + q) << 10;   // element base
        float4 v = *(const float4*)(S + rowe + tid * 4);

        float m = fmaxf(fmaxf(v.x, v.y), fmaxf(v.z, v.w));
#pragma unroll
        for (int o = 16; o; o >>= 1) m = fmaxf(m, __shfl_xor_sync(0xffffffffu, m, o));
        if ((tid & 31) == 0) red[tid >> 5] = m;
        __syncthreads();
        if (tid < 8) {
            m = red[tid];
#pragma unroll
            for (int o = 4; o; o >>= 1) m = fmaxf(m, __shfl_xor_sync(0xffu, m, o));
            if (tid == 0) bcast = m;
        }
        __syncthreads();
        m = bcast;

        v.x = __expf(v.x - m); v.y = __expf(v.y - m);
        v.z = __expf(v.z - m); v.w = __expf(v.w - m);
        float s = (v.x + v.y) + (v.z + v.w);
#pragma unroll
        for (int o = 16; o; o >>= 1) s += __shfl_xor_sync(0xffffffffu, s, o);
        __syncthreads();
        if ((tid & 31) == 0) red[tid >> 5] = s;
        __syncthreads();
        if (tid < 8) {
            s = red[tid];
#pragma unroll
            for (int o = 4; o; o >>= 1) s += __shfl_xor_sync(0xffu, s, o);
            if (tid == 0) bcast = s;
        }
        __syncthreads();
        const float inv = 1.0f / bcast;

        v.x *= inv; v.y *= inv; v.z *= inv; v.w *= inv;
        macc.x += v.x; macc.y += v.y; macc.z += v.z; macc.w += v.w;

        __nv_bfloat16 h0 = __float2bfloat16(v.x);
        __nv_bfloat16 h1 = __float2bfloat16(v.y);
        __nv_bfloat16 h2 = __float2bfloat16(v.z);
        __nv_bfloat16 h3 = __float2bfloat16(v.w);
        const size_t r2 = rowe >> 1;   // bfloat162 units
        ph[r2 + tid * 2 + 0] = __halves2bfloat162(h0, h1);
        ph[r2 + tid * 2 + 1] = __halves2bfloat162(h2, h3);
        pl[r2 + tid * 2 + 0] = __halves2bfloat162(
            __float2bfloat16(v.x - __bfloat162float(h0)),
            __float2bfloat16(v.y - __bfloat162float(h1)));
        pl[r2 + tid * 2 + 1] = __halves2bfloat162(
            __float2bfloat16(v.z - __bfloat162float(h2)),
            __float2bfloat16(v.w - __bfloat162float(h3)));
        __syncthreads();   // protect red/bcast for next head
    }

    const float inv16 = 1.0f / HH_;
    macc.x *= inv16; macc.y *= inv16; macc.z *= inv16; macc.w *= inv16;
    *(float4*)(mean_out + (((size_t)bq) << 10) + tid * 4) = macc;
}

// ---------------------------------------------------------------------------
// out = LayerNorm(query + attn_out) * gamma + beta.  One block per row.
// ---------------------------------------------------------------------------
__global__ void residual_ln(const float* __restrict__ q, const float* __restrict__ ao,
                            const float* __restrict__ gamma, const float* __restrict__ beta,
                            float* __restrict__ out)
{
    __shared__ float red[8];
    __shared__ float bcast;
    const long row = blockIdx.x;
    const int tid = threadIdx.x;

    float4 qa = *(const float4*)&q [row * DD + tid * 4];
    float4 aa = *(const float4*)&ao[row * DD + tid * 4];
    float x0 = qa.x + aa.x, x1 = qa.y + aa.y, x2 = qa.z + aa.z, x3 = qa.w + aa.w;

    float s = (x0 + x1) + (x2 + x3);
#pragma unroll
    for (int o = 16; o; o >>= 1) s += __shfl_xor_sync(0xffffffffu, s, o);
    if ((tid & 31) == 0) red[tid >> 5] = s;
    __syncthreads();
    if (tid < 8) {
        s = red[tid];
#pragma unroll
        for (int o = 4; o; o >>= 1) s += __shfl_xor_sync(0xffu, s, o);
        if (tid == 0) bcast = s;
    }
    __syncthreads();
    const float mu = bcast * (1.0f / DD);

    float d0 = x0 - mu, d1 = x1 - mu, d2 = x2 - mu, d3 = x3 - mu;
    float sq = (d0 * d0 + d1 * d1) + (d2 * d2 + d3 * d3);
#pragma unroll
    for (int o = 16; o; o >>= 1) sq += __shfl_xor_sync(0xffffffffu, sq, o);
    __syncthreads();
    if ((tid & 31) == 0) red[tid >> 5] = sq;
    __syncthreads();
    if (tid < 8) {
        sq = red[tid];
#pragma unroll
        for (int o = 4; o; o >>= 1) sq += __shfl_xor_sync(0xffu, sq, o);
        if (tid == 0) bcast = sq;
    }
    __syncthreads();
    const float rstd = rsqrtf(bcast * (1.0f / DD) + LN_EPS);

    float4 g = *(const float4*)&gamma[tid * 4];
    float4 be = *(const float4*)&beta[tid * 4];
    float4 o4;
    o4.x = d0 * rstd * g.x + be.x;
    o4.y = d1 * rstd * g.y + be.y;
    o4.z = d2 * rstd * g.z + be.z;
    o4.w = d3 * rstd * g.w + be.w;
    *(float4*)&out[row * DD + tid * 4] = o4;
}

// ---------------------------------------------------------------------------
extern "C" void kernel_launch(void* const* d_in, const int* in_sizes, int n_in,
                              void* d_out, int out_size)
{
    const float* query = (const float*)d_in[0];
    const float* key_  = (const float*)d_in[1];
    const float* value = (const float*)d_in[2];
    const float* in_w  = (const float*)d_in[3];   // [3D, D]
    const float* in_b  = (const float*)d_in[4];   // [3D]
    const float* out_w = (const float*)d_in[5];   // [D, D]
    const float* out_b = (const float*)d_in[6];   // [D]
    const float* gamma = (const float*)d_in[7];
    const float* beta  = (const float*)d_in[8];
    float* out = (float*)d_out;

    float *Q, *K, *V, *S, *CTX, *AO;
    cudaGetSymbolAddress((void**)&Q,   g_Q);
    cudaGetSymbolAddress((void**)&K,   g_K);
    cudaGetSymbolAddress((void**)&V,   g_V);
    cudaGetSymbolAddress((void**)&S,   g_S);
    cudaGetSymbolAddress((void**)&CTX, g_CTX);
    cudaGetSymbolAddress((void**)&AO,  g_AO);

    __nv_bfloat16 *qh, *ql, *kh, *kl, *vh, *vl, *wh, *wl, *woh, *wol, *ch, *cl, *ph, *pl;
    cudaGetSymbolAddress((void**)&qh,  g_qh);  cudaGetSymbolAddress((void**)&ql,  g_ql);
    cudaGetSymbolAddress((void**)&kh,  g_kh);  cudaGetSymbolAddress((void**)&kl,  g_kl);
    cudaGetSymbolAddress((void**)&vh,  g_vh);  cudaGetSymbolAddress((void**)&vl,  g_vl);
    cudaGetSymbolAddress((void**)&wh,  g_wh);  cudaGetSymbolAddress((void**)&wl,  g_wl);
    cudaGetSymbolAddress((void**)&woh, g_woh); cudaGetSymbolAddress((void**)&wol, g_wol);
    cudaGetSymbolAddress((void**)&ch,  g_ch);  cudaGetSymbolAddress((void**)&cl,  g_cl);
    cudaGetSymbolAddress((void**)&ph,  g_ph);  cudaGetSymbolAddress((void**)&pl,  g_pl);

    const float qscale = 0.125f;  // 1/sqrt(hd)

    auto launch_split = [](const float* x, __nv_bfloat16* h, __nv_bfloat16* l, long n) {
        int n4 = (int)(n / 4);
        split_bf16<<<(n4 + 255) / 256, 256>>>((const float4*)x, (__nv_bfloat162*)h,
                                              (__nv_bfloat162*)l, n4);
    };

    // 1) split inputs + weights
    launch_split(query, qh, ql, (long)BB * LQ  * DD);
    launch_split(key_,  kh, kl, (long)BB * LKV * DD);
    launch_split(value, vh, vl, (long)BB * LKV * DD);
    launch_split(in_w,  wh, wl, 3L * DD * DD);
    launch_split(out_w, woh, wol, (long)DD * DD);

    // 2) Q/K/V projections (HMMA bf16x3)
    gemm_mma<<<dim3(DD / 128, (BB * LQ) / 128),  256>>>(
        qh, ql, wh,               wl,               in_b,        Q, qscale);
    gemm_mma<<<dim3(DD / 128, (BB * LKV) / 128), 256>>>(
        kh, kl, wh + (long)DD*DD, wl + (long)DD*DD, in_b + DD,   K, 1.0f);
    gemm_mma<<<dim3(DD / 128, (BB * LKV) / 128), 256>>>(
        vh, vl, wh + 2L*DD*DD,    wl + 2L*DD*DD,    in_b + 2*DD, V, 1.0f);

    // 3) re-split projections into the (now free) input-split buffers
    launch_split(Q, qh, ql, (long)BB * LQ  * DD);   // projected Q hi/lo
    launch_split(K, kh, kl, (long)BB * LKV * DD);   // projected K hi/lo
    transpose_split_v<<<dim3(LKV / 32, HD / 32, BB * HH_), 256>>>(V, vh, vl);  // Vt hi/lo

    // 4) scores on tensor cores -> fp32 S
    scores_mma<<<dim3(LKV / 128, LQ / 128, BB * HH_), 256>>>(qh, ql, kh, kl, S);

    // 5) fused softmax + head-mean; probs emitted as bf16 hi/lo
    softmax_meanheads<<<BB * LQ, 256>>>(S, (__nv_bfloat162*)ph, (__nv_bfloat162*)pl,
                                        out + (long)BB * LQ * DD);

    // 6) ctx on tensor cores -> CTX [B,Lq,D]
    ctx_mma<<<dim3(1, LQ / 128, BB * HH_), 256>>>(ph, pl, vh, vl, CTX);

    // 7) out projection (HMMA bf16x3)
    launch_split(CTX, ch, cl, (long)BB * LQ * DD);
    gemm_mma<<<dim3(DD / 128, (BB * LQ) / 128), 256>>>(
        ch, cl, woh, wol, out_b, AO, 1.0f);

    // 8) residual + LayerNorm
    residual_ln<<<BB * LQ, 256>>>(query, AO, gamma, beta, out);
}

// round 5
// speedup vs baseline: 2.5978x; 1.2078x over previous
#include <cuda_runtime.h>
#include <cuda_bf16.h>
#include <math.h>
#include <stdint.h>

// Problem constants
#define BB   8
#define LQ   512
#define LKV  1024
#define DD   1024
#define HH_  16
#define HD   64
#define LN_EPS 1e-5f

// ---------------------------------------------------------------------------
// Scratch (device globals: allocation-free per harness rules)
// ---------------------------------------------------------------------------
__device__ float g_V  [BB * LKV * DD];               // fp32 v proj
__device__ float g_S  [(size_t)BB * HH_ * LQ * LKV]; // fp32 scores
__device__ float g_AO [BB * LQ  * DD];               // fp32 attn_out

// bf16 hi/lo buffers
__device__ __align__(16) __nv_bfloat16 g_qh [BB * LQ  * DD], g_ql [BB * LQ  * DD]; // input q split
__device__ __align__(16) __nv_bfloat16 g_kh [BB * LKV * DD], g_kl [BB * LKV * DD]; // input k split
__device__ __align__(16) __nv_bfloat16 g_vh [BB * LKV * DD], g_vl [BB * LKV * DD]; // input v split -> later Vt split
__device__ __align__(16) __nv_bfloat16 g_wh [3 * DD * DD],   g_wl [3 * DD * DD];
__device__ __align__(16) __nv_bfloat16 g_woh[DD * DD],       g_wol[DD * DD];
__device__ __align__(16) __nv_bfloat16 g_qh2[BB * LQ  * DD], g_ql2[BB * LQ  * DD]; // Q proj split
__device__ __align__(16) __nv_bfloat16 g_kh2[BB * LKV * DD], g_kl2[BB * LKV * DD]; // K proj split
__device__ __align__(16) __nv_bfloat16 g_ch [BB * LQ  * DD], g_cl [BB * LQ  * DD]; // ctx split
__device__ __align__(16) __nv_bfloat16 g_ph [(size_t)BB * HH_ * LQ * LKV];          // probs hi
__device__ __align__(16) __nv_bfloat16 g_pl [(size_t)BB * HH_ * LQ * LKV];          // probs lo

// ---------------------------------------------------------------------------
// Baseline-PTX tensor-core helpers (NO tcgen05 — compute_103 target!)
// ---------------------------------------------------------------------------
__device__ __forceinline__ uint32_t smem_u32(const void* p) {
    uint32_t a;
    asm("{ .reg .u64 t; cvta.to.shared.u64 t, %1; cvt.u32.u64 %0, t; }" : "=r"(a) : "l"(p));
    return a;
}
__device__ __forceinline__ void ldsm4(uint32_t& r0, uint32_t& r1, uint32_t& r2,
                                      uint32_t& r3, uint32_t a) {
    asm volatile("ldmatrix.sync.aligned.m8n8.x4.shared.b16 {%0,%1,%2,%3}, [%4];"
                 : "=r"(r0), "=r"(r1), "=r"(r2), "=r"(r3) : "r"(a));
}
__device__ __forceinline__ void mma_bf16(float* d, const uint32_t* a, const uint32_t* b) {
    asm volatile("mma.sync.aligned.m16n8k16.row.col.f32.bf16.bf16.f32 "
                 "{%0,%1,%2,%3},{%4,%5,%6,%7},{%8,%9},{%0,%1,%2,%3};"
                 : "+f"(d[0]), "+f"(d[1]), "+f"(d[2]), "+f"(d[3])
                 : "r"(a[0]), "r"(a[1]), "r"(a[2]), "r"(a[3]), "r"(b[0]), "r"(b[1]));
}
#define CP_ASYNC16(s, g) \
    asm volatile("cp.async.cg.shared.global [%0], [%1], 16;" :: "r"(s), "l"(g))
#define CP_COMMIT() asm volatile("cp.async.commit_group;" ::: "memory")
#define CP_WAIT1()  asm volatile("cp.async.wait_group 1;"  ::: "memory")

// 128B-row XOR swizzle: 16B chunk c (0..7), row r -> conflict-free ldmatrix & stores
__device__ __forceinline__ uint32_t sw128(int r, int c) {
    return (uint32_t)(r * 128 + ((c ^ (r & 7)) << 4));
}

// split helper: v -> (hi, lo) bf16
__device__ __forceinline__ void bsplit(float v, __nv_bfloat16& h, __nv_bfloat16& l) {
    h = __float2bfloat16(v);
    l = __float2bfloat16(v - __bfloat162float(h));
}

// ---------------------------------------------------------------------------
// fp32 -> bf16 hi/lo split (bf16x3 scheme)
// ---------------------------------------------------------------------------
__global__ void split_bf16(const float4* __restrict__ x,
                           __nv_bfloat162* __restrict__ hi,
                           __nv_bfloat162* __restrict__ lo, int n4)
{
    int i = blockIdx.x * blockDim.x + threadIdx.x;
    if (i >= n4) return;
    float4 v = x[i];
    __nv_bfloat16 h0, h1, h2, h3, l0, l1, l2, l3;
    bsplit(v.x, h0, l0); bsplit(v.y, h1, l1);
    bsplit(v.z, h2, l2); bsplit(v.w, h3, l3);
    hi[i * 2 + 0] = __halves2bfloat162(h0, h1);
    hi[i * 2 + 1] = __halves2bfloat162(h2, h3);
    lo[i * 2 + 0] = __halves2bfloat162(l0, l1);
    lo[i * 2 + 1] = __halves2bfloat162(l2, l3);
}

// ---------------------------------------------------------------------------
// Transpose + split V: fp32 V[b*Lkv + k][h*64 + n] -> Vt hi/lo [(b*16+h)*64 + n][k]
// ---------------------------------------------------------------------------
__global__ void transpose_split_v(const float* __restrict__ V,
                                  __nv_bfloat16* __restrict__ hi,
                                  __nv_bfloat16* __restrict__ lo)
{
    __shared__ float t[32][33];
    const int z = blockIdx.z, b = z >> 4, h = z & 15;
    const int k0 = blockIdx.x * 32, nn0 = blockIdx.y * 32;
    const int tx = threadIdx.x & 31, ty = threadIdx.x >> 5;   // ty 0..7
#pragma unroll
    for (int i = 0; i < 4; ++i) {
        int k = k0 + ty + i * 8;
        t[ty + i * 8][tx] = V[(((size_t)(b * 1024 + k)) << 10) + h * 64 + nn0 + tx];
    }
    __syncthreads();
#pragma unroll
    for (int i = 0; i < 4; ++i) {
        int n = nn0 + ty + i * 8;
        float v = t[tx][ty + i * 8];
        __nv_bfloat16 hh, ll;
        bsplit(v, hh, ll);
        size_t o = (((size_t)(z * 64 + n)) << 10) + k0 + tx;
        hi[o] = hh;
        lo[o] = ll;
    }
}

// ---------------------------------------------------------------------------
// Unified HMMA bf16x3 GEMM, BK=64, 3-stage cp.async, single sync per iter.
//   C = scale * (A @ B^T + bias), A [M rows][1024], B [N rows][1024], ldc=1024.
//   KCH: k-chunks of 64 per part (16 for K=1024, 1 for K=64). NIT = 3*KCH.
//   Batched via blockIdx.z decomposed as (z>>4, z&15) with per-operand strides.
//   SPLIT_OUT: write bf16 hi/lo instead of fp32.
// Block 128x128, 8 warps (2x4), warp tile 64x32. Dyn smem = 3*32KB.
// ---------------------------------------------------------------------------
template<int KCH, bool SPLIT_OUT>
__global__ void __launch_bounds__(256, 2) gemm64(
    const __nv_bfloat16* __restrict__ Ahi, const __nv_bfloat16* __restrict__ Alo,
    const __nv_bfloat16* __restrict__ Bhi, const __nv_bfloat16* __restrict__ Blo,
    const float* __restrict__ bias, float* __restrict__ Cf,
    __nv_bfloat16* __restrict__ Chi, __nv_bfloat16* __restrict__ Clo, float scale,
    long sA0, long sA1, long sB0, long sB1, long sC0, long sC1)
{
    extern __shared__ __align__(16) char dynsm[];
    const uint32_t smBase = smem_u32(dynsm);

    const int tid  = threadIdx.x;
    const int lane = tid & 31;
    const int wid  = tid >> 5;
    const int wr   = wid >> 2;
    const int wc   = wid & 3;
    const int z    = blockIdx.z;
    const int m0   = blockIdx.y * 128;
    const int n0   = blockIdx.x * 128;
    const size_t aOff = (size_t)(z >> 4) * sA0 + (size_t)(z & 15) * sA1;
    const size_t bOff = (size_t)(z >> 4) * sB0 + (size_t)(z & 15) * sB1;
    const size_t cOff = (size_t)(z >> 4) * sC0 + (size_t)(z & 15) * sC1;

    const int rA  = lane & 15;
    const int cAh = lane >> 4;
    const int rBl = (lane & 7) + ((lane & 16) >> 1);
    const int cBh = (lane >> 3) & 1;

    float acc[4][4][4];
#pragma unroll
    for (int mt = 0; mt < 4; ++mt)
#pragma unroll
        for (int nt = 0; nt < 4; ++nt)
#pragma unroll
            for (int j = 0; j < 4; ++j) acc[mt][nt][j] = 0.f;

    auto prefetch = [&](int it, int stage) {
        const int part = it / KCH;
        const int ko   = (it % KCH) << 6;
        const __nv_bfloat16* Ap = (part == 2) ? Alo : Ahi;
        const __nv_bfloat16* Bp = (part == 1) ? Blo : Bhi;
        const uint32_t as = smBase + (uint32_t)stage * 32768u;
        const uint32_t bs = as + 16384u;
#pragma unroll
        for (int i = 0; i < 4; ++i) {
            int q = i * 256 + tid;
            int r = q >> 3, c = q & 7;
            CP_ASYNC16(as + sw128(r, c),
                       Ap + aOff + (((size_t)(m0 + r)) << 10) + ko + c * 8);
            CP_ASYNC16(bs + sw128(r, c),
                       Bp + bOff + (((size_t)(n0 + r)) << 10) + ko + c * 8);
        }
        CP_COMMIT();
    };

    const int NIT = 3 * KCH;
    prefetch(0, 0);
    prefetch(1, 1);

    for (int it = 0; it < NIT; ++it) {
        CP_WAIT1();
        __syncthreads();
        if (it + 2 < NIT) prefetch(it + 2, (it + 2) % 3);
        else CP_COMMIT();

        const uint32_t aT = smBase + (uint32_t)(it % 3) * 32768u;
        const uint32_t bT = aT + 16384u;

#pragma unroll
        for (int ks = 0; ks < 4; ++ks) {
            uint32_t af[4][4];
            uint32_t bf[4][2];
#pragma unroll
            for (int mt = 0; mt < 4; ++mt) {
                int r = wr * 64 + mt * 16 + rA;
                ldsm4(af[mt][0], af[mt][1], af[mt][2], af[mt][3],
                      aT + sw128(r, ks * 2 + cAh));
            }
#pragma unroll
            for (int tp = 0; tp < 2; ++tp) {
                int r = wc * 32 + tp * 16 + rBl;
                uint32_t x0, x1, x2, x3;
                ldsm4(x0, x1, x2, x3, bT + sw128(r, ks * 2 + cBh));
                bf[tp * 2][0] = x0;     bf[tp * 2][1] = x1;
                bf[tp * 2 + 1][0] = x2; bf[tp * 2 + 1][1] = x3;
            }
#pragma unroll
            for (int mt = 0; mt < 4; ++mt)
#pragma unroll
                for (int nt = 0; nt < 4; ++nt)
                    mma_bf16(acc[mt][nt], af[mt], bf[nt]);
        }
    }
    __syncthreads();

#pragma unroll
    for (int mt = 0; mt < 4; ++mt) {
        const int row = m0 + wr * 64 + mt * 16 + (lane >> 2);
#pragma unroll
        for (int nt = 0; nt < 4; ++nt) {
            const int col = n0 + wc * 32 + nt * 8 + (lane & 3) * 2;
            const float b0 = bias ? bias[col]     : 0.f;
            const float b1 = bias ? bias[col + 1] : 0.f;
            const float v0 = (acc[mt][nt][0] + b0) * scale;
            const float v1 = (acc[mt][nt][1] + b1) * scale;
            const float v2 = (acc[mt][nt][2] + b0) * scale;
            const float v3 = (acc[mt][nt][3] + b1) * scale;
            const size_t i0 = cOff + ((size_t)row << 10) + col;
            const size_t i1 = i0 + (8 << 10);
            if (SPLIT_OUT) {
                __nv_bfloat16 h0, h1, h2, h3, l0, l1, l2, l3;
                bsplit(v0, h0, l0); bsplit(v1, h1, l1);
                bsplit(v2, h2, l2); bsplit(v3, h3, l3);
                *(__nv_bfloat162*)(Chi + i0) = __halves2bfloat162(h0, h1);
                *(__nv_bfloat162*)(Clo + i0) = __halves2bfloat162(l0, l1);
                *(__nv_bfloat162*)(Chi + i1) = __halves2bfloat162(h2, h3);
                *(__nv_bfloat162*)(Clo + i1) = __halves2bfloat162(l2, l3);
            } else {
                Cf[i0] = v0; Cf[i0 + 1] = v1;
                Cf[i1] = v2; Cf[i1 + 1] = v3;
            }
        }
    }
}

// ---------------------------------------------------------------------------
// ctx GEMM: per z=(b,h)  ctx[512,64] = P[512,1024] @ Vt[64,1024]^T, BK=64,
// block 128x64, warp tile 64x16, 3-stage, single sync. Writes bf16 hi/lo into
// [b*512+row][h*64+col] layout. Dyn smem = 3*24KB.
// ---------------------------------------------------------------------------
__global__ void __launch_bounds__(256, 2) ctx64(
    const __nv_bfloat16* __restrict__ Phi, const __nv_bfloat16* __restrict__ Plo,
    const __nv_bfloat16* __restrict__ Vhi, const __nv_bfloat16* __restrict__ Vlo,
    __nv_bfloat16* __restrict__ Chi, __nv_bfloat16* __restrict__ Clo)
{
    extern __shared__ __align__(16) char dynsm[];
    const uint32_t smBase = smem_u32(dynsm);

    const int tid  = threadIdx.x;
    const int lane = tid & 31;
    const int wid  = tid >> 5;
    const int wr   = wid >> 2;   // 0..1 (64 rows)
    const int wc   = wid & 3;    // 0..3 (16 cols)
    const int z    = blockIdx.z, b = z >> 4, h = z & 15;
    const int m0   = blockIdx.y * 128;
    const size_t aOff = ((size_t)z * 512) << 10;
    const size_t bOff = ((size_t)z * 64) << 10;

    const int rA  = lane & 15;
    const int cAh = lane >> 4;
    const int rBl = (lane & 7) + ((lane & 16) >> 1);
    const int cBh = (lane >> 3) & 1;

    float acc[4][2][4];
#pragma unroll
    for (int mt = 0; mt < 4; ++mt)
#pragma unroll
        for (int nt = 0; nt < 2; ++nt)
#pragma unroll
            for (int j = 0; j < 4; ++j) acc[mt][nt][j] = 0.f;

    auto prefetch = [&](int it, int stage) {
        const int part = it >> 4;
        const int ko   = (it & 15) << 6;
        const __nv_bfloat16* Ap = (part == 2) ? Plo : Phi;
        const __nv_bfloat16* Bp = (part == 1) ? Vlo : Vhi;
        const uint32_t as = smBase + (uint32_t)stage * 24576u;
        const uint32_t bs = as + 16384u;
#pragma unroll
        for (int i = 0; i < 4; ++i) {
            int q = i * 256 + tid;
            int r = q >> 3, c = q & 7;
            CP_ASYNC16(as + sw128(r, c),
                       Ap + aOff + (((size_t)(m0 + r)) << 10) + ko + c * 8);
        }
#pragma unroll
        for (int i = 0; i < 2; ++i) {
            int q = i * 256 + tid;
            int r = q >> 3, c = q & 7;
            CP_ASYNC16(bs + sw128(r, c),
                       Bp + bOff + (((size_t)r) << 10) + ko + c * 8);
        }
        CP_COMMIT();
    };

    const int NIT = 48;
    prefetch(0, 0);
    prefetch(1, 1);

    for (int it = 0; it < NIT; ++it) {
        CP_WAIT1();
        __syncthreads();
        if (it + 2 < NIT) prefetch(it + 2, (it + 2) % 3);
        else CP_COMMIT();

        const uint32_t aT = smBase + (uint32_t)(it % 3) * 24576u;
        const uint32_t bT = aT + 16384u;

#pragma unroll
        for (int ks = 0; ks < 4; ++ks) {
            uint32_t af[4][4];
            uint32_t bf[2][2];
#pragma unroll
            for (int mt = 0; mt < 4; ++mt) {
                int r = wr * 64 + mt * 16 + rA;
                ldsm4(af[mt][0], af[mt][1], af[mt][2], af[mt][3],
                      aT + sw128(r, ks * 2 + cAh));
            }
            {
                int r = wc * 16 + rBl;
                uint32_t x0, x1, x2, x3;
                ldsm4(x0, x1, x2, x3, bT + sw128(r, ks * 2 + cBh));
                bf[0][0] = x0; bf[0][1] = x1;
                bf[1][0] = x2; bf[1][1] = x3;
            }
#pragma unroll
            for (int mt = 0; mt < 4; ++mt)
#pragma unroll
                for (int nt = 0; nt < 2; ++nt)
                    mma_bf16(acc[mt][nt], af[mt], bf[nt]);
        }
    }
    __syncthreads();

#pragma unroll
    for (int mt = 0; mt < 4; ++mt) {
        const int row = m0 + wr * 64 + mt * 16 + (lane >> 2);
#pragma unroll
        for (int nt = 0; nt < 2; ++nt) {
            const int col = wc * 16 + nt * 8 + (lane & 3) * 2;
            const size_t i0 = (((size_t)(b * 512 + row)) << 10) + h * 64 + col;
            const size_t i1 = i0 + (8 << 10);
            __nv_bfloat16 h0, h1, h2, h3, l0, l1, l2, l3;
            bsplit(acc[mt][nt][0], h0, l0); bsplit(acc[mt][nt][1], h1, l1);
            bsplit(acc[mt][nt][2], h2, l2); bsplit(acc[mt][nt][3], h3, l3);
            *(__nv_bfloat162*)(Chi + i0) = __halves2bfloat162(h0, h1);
            *(__nv_bfloat162*)(Clo + i0) = __halves2bfloat162(l0, l1);
            *(__nv_bfloat162*)(Chi + i1) = __halves2bfloat162(h2, h3);
            *(__nv_bfloat162*)(Clo + i1) = __halves2bfloat162(l2, l3);
        }
    }
}

// ---------------------------------------------------------------------------
// Fused softmax + head-mean. One block per (b,q); loops over 16 heads.
// ---------------------------------------------------------------------------
__global__ void softmax_meanheads(const float* __restrict__ S,
                                  __nv_bfloat162* __restrict__ ph,
                                  __nv_bfloat162* __restrict__ pl,
                                  float* __restrict__ mean_out)
{
    __shared__ float red[8];
    __shared__ float bcast;
    const int bq = blockIdx.x;
    const int b = bq >> 9, q = bq & 511;
    const int tid = threadIdx.x;

    float4 macc = make_float4(0.f, 0.f, 0.f, 0.f);

#pragma unroll 1
    for (int h = 0; h < HH_; ++h) {
        const size_t rowe = ((size_t)(b * 16 + h) * 512 + q) << 10;
        float4 v = *(const float4*)(S + rowe + tid * 4);

        float m = fmaxf(fmaxf(v.x, v.y), fmaxf(v.z, v.w));
#pragma unroll
        for (int o = 16; o; o >>= 1) m = fmaxf(m, __shfl_xor_sync(0xffffffffu, m, o));
        if ((tid & 31) == 0) red[tid >> 5] = m;
        __syncthreads();
        if (tid < 8) {
            m = red[tid];
#pragma unroll
            for (int o = 4; o; o >>= 1) m = fmaxf(m, __shfl_xor_sync(0xffu, m, o));
            if (tid == 0) bcast = m;
        }
        __syncthreads();
        m = bcast;

        v.x = __expf(v.x - m); v.y = __expf(v.y - m);
        v.z = __expf(v.z - m); v.w = __expf(v.w - m);
        float s = (v.x + v.y) + (v.z + v.w);
#pragma unroll
        for (int o = 16; o; o >>= 1) s += __shfl_xor_sync(0xffffffffu, s, o);
        __syncthreads();
        if ((tid & 31) == 0) red[tid >> 5] = s;
        __syncthreads();
        if (tid < 8) {
            s = red[tid];
#pragma unroll
            for (int o = 4; o; o >>= 1) s += __shfl_xor_sync(0xffu, s, o);
            if (tid == 0) bcast = s;
        }
        __syncthreads();
        const float inv = 1.0f / bcast;

        v.x *= inv; v.y *= inv; v.z *= inv; v.w *= inv;
        macc.x += v.x; macc.y += v.y; macc.z += v.z; macc.w += v.w;

        __nv_bfloat16 h0, h1, h2, h3, l0, l1, l2, l3;
        bsplit(v.x, h0, l0); bsplit(v.y, h1, l1);
        bsplit(v.z, h2, l2); bsplit(v.w, h3, l3);
        const size_t r2 = rowe >> 1;
        ph[r2 + tid * 2 + 0] = __halves2bfloat162(h0, h1);
        ph[r2 + tid * 2 + 1] = __halves2bfloat162(h2, h3);
        pl[r2 + tid * 2 + 0] = __halves2bfloat162(l0, l1);
        pl[r2 + tid * 2 + 1] = __halves2bfloat162(l2, l3);
        __syncthreads();
    }

    const float inv16 = 1.0f / HH_;
    macc.x *= inv16; macc.y *= inv16; macc.z *= inv16; macc.w *= inv16;
    *(float4*)(mean_out + (((size_t)bq) << 10) + tid * 4) = macc;
}

// ---------------------------------------------------------------------------
// out = LayerNorm(query + attn_out) * gamma + beta.  One block per row.
// ---------------------------------------------------------------------------
__global__ void residual_ln(const float* __restrict__ q, const float* __restrict__ ao,
                            const float* __restrict__ gamma, const float* __restrict__ beta,
                            float* __restrict__ out)
{
    __shared__ float red[8];
    __shared__ float bcast;
    const long row = blockIdx.x;
    const int tid = threadIdx.x;

    float4 qa = *(const float4*)&q [row * DD + tid * 4];
    float4 aa = *(const float4*)&ao[row * DD + tid * 4];
    float x0 = qa.x + aa.x, x1 = qa.y + aa.y, x2 = qa.z + aa.z, x3 = qa.w + aa.w;

    float s = (x0 + x1) + (x2 + x3);
#pragma unroll
    for (int o = 16; o; o >>= 1) s += __shfl_xor_sync(0xffffffffu, s, o);
    if ((tid & 31) == 0) red[tid >> 5] = s;
    __syncthreads();
    if (tid < 8) {
        s = red[tid];
#pragma unroll
        for (int o = 4; o; o >>= 1) s += __shfl_xor_sync(0xffu, s, o);
        if (tid == 0) bcast = s;
    }
    __syncthreads();
    const float mu = bcast * (1.0f / DD);

    float d0 = x0 - mu, d1 = x1 - mu, d2 = x2 - mu, d3 = x3 - mu;
    float sq = (d0 * d0 + d1 * d1) + (d2 * d2 + d3 * d3);
#pragma unroll
    for (int o = 16; o; o >>= 1) sq += __shfl_xor_sync(0xffffffffu, sq, o);
    __syncthreads();
    if ((tid & 31) == 0) red[tid >> 5] = sq;
    __syncthreads();
    if (tid < 8) {
        sq = red[tid];
#pragma unroll
        for (int o = 4; o; o >>= 1) sq += __shfl_xor_sync(0xffu, sq, o);
        if (tid == 0) bcast = sq;
    }
    __syncthreads();
    const float rstd = rsqrtf(bcast * (1.0f / DD) + LN_EPS);

    float4 g = *(const float4*)&gamma[tid * 4];
    float4 be = *(const float4*)&beta[tid * 4];
    float4 o4;
    o4.x = d0 * rstd * g.x + be.x;
    o4.y = d1 * rstd * g.y + be.y;
    o4.z = d2 * rstd * g.z + be.z;
    o4.w = d3 * rstd * g.w + be.w;
    *(float4*)&out[row * DD + tid * 4] = o4;
}

// ---------------------------------------------------------------------------
extern "C" void kernel_launch(void* const* d_in, const int* in_sizes, int n_in,
                              void* d_out, int out_size)
{
    const float* query = (const float*)d_in[0];
    const float* key_  = (const float*)d_in[1];
    const float* value = (const float*)d_in[2];
    const float* in_w  = (const float*)d_in[3];
    const float* in_b  = (const float*)d_in[4];
    const float* out_w = (const float*)d_in[5];
    const float* out_b = (const float*)d_in[6];
    const float* gamma = (const float*)d_in[7];
    const float* beta  = (const float*)d_in[8];
    float* out = (float*)d_out;

    float *V, *S, *AO;
    cudaGetSymbolAddress((void**)&V,  g_V);
    cudaGetSymbolAddress((void**)&S,  g_S);
    cudaGetSymbolAddress((void**)&AO, g_AO);

    __nv_bfloat16 *qh, *ql, *kh, *kl, *vh, *vl, *wh, *wl, *woh, *wol;
    __nv_bfloat16 *qh2, *ql2, *kh2, *kl2, *ch, *cl, *ph, *pl;
    cudaGetSymbolAddress((void**)&qh,  g_qh);  cudaGetSymbolAddress((void**)&ql,  g_ql);
    cudaGetSymbolAddress((void**)&kh,  g_kh);  cudaGetSymbolAddress((void**)&kl,  g_kl);
    cudaGetSymbolAddress((void**)&vh,  g_vh);  cudaGetSymbolAddress((void**)&vl,  g_vl);
    cudaGetSymbolAddress((void**)&wh,  g_wh);  cudaGetSymbolAddress((void**)&wl,  g_wl);
    cudaGetSymbolAddress((void**)&woh, g_woh); cudaGetSymbolAddress((void**)&wol, g_wol);
    cudaGetSymbolAddress((void**)&qh2, g_qh2); cudaGetSymbolAddress((void**)&ql2, g_ql2);
    cudaGetSymbolAddress((void**)&kh2, g_kh2); cudaGetSymbolAddress((void**)&kl2, g_kl2);
    cudaGetSymbolAddress((void**)&ch,  g_ch);  cudaGetSymbolAddress((void**)&cl,  g_cl);
    cudaGetSymbolAddress((void**)&ph,  g_ph);  cudaGetSymbolAddress((void**)&pl,  g_pl);

    const int SM_G = 3 * 32768;   // gemm64 dynamic smem
    const int SM_C = 3 * 24576;   // ctx64 dynamic smem
    cudaFuncSetAttribute(gemm64<16, true>,  cudaFuncAttributeMaxDynamicSharedMemorySize, SM_G);
    cudaFuncSetAttribute(gemm64<16, false>, cudaFuncAttributeMaxDynamicSharedMemorySize, SM_G);
    cudaFuncSetAttribute(gemm64<1,  false>, cudaFuncAttributeMaxDynamicSharedMemorySize, SM_G);
    cudaFuncSetAttribute(ctx64, cudaFuncAttributeMaxDynamicSharedMemorySize, SM_C);

    const float qscale = 0.125f;  // 1/sqrt(hd)

    auto launch_split = [](const float* x, __nv_bfloat16* h, __nv_bfloat16* l, long n) {
        int n4 = (int)(n / 4);
        split_bf16<<<(n4 + 255) / 256, 256>>>((const float4*)x, (__nv_bfloat162*)h,
                                              (__nv_bfloat162*)l, n4);
    };

    // 1) split inputs + weights
    launch_split(query, qh, ql, (long)BB * LQ  * DD);
    launch_split(key_,  kh, kl, (long)BB * LKV * DD);
    launch_split(value, vh, vl, (long)BB * LKV * DD);
    launch_split(in_w,  wh, wl, 3L * DD * DD);
    launch_split(out_w, woh, wol, (long)DD * DD);

    // 2) Q/K projections -> bf16 hi/lo directly; V projection -> fp32
    gemm64<16, true><<<dim3(8, 32, 1), 256, SM_G>>>(
        qh, ql, wh, wl, in_b, nullptr, qh2, ql2, qscale, 0,0, 0,0, 0,0);
    gemm64<16, true><<<dim3(8, 64, 1), 256, SM_G>>>(
        kh, kl, wh + (long)DD*DD, wl + (long)DD*DD, in_b + DD,
        nullptr, kh2, kl2, 1.0f, 0,0, 0,0, 0,0);
    gemm64<16, false><<<dim3(8, 64, 1), 256, SM_G>>>(
        vh, vl, wh + 2L*DD*DD, wl + 2L*DD*DD, in_b + 2*DD,
        V, nullptr, nullptr, 1.0f, 0,0, 0,0, 0,0);

    // 3) transpose + split V into head-major Vt (reuses input-v split buffers)
    transpose_split_v<<<dim3(LKV / 32, HD / 32, BB * HH_), 256>>>(V, vh, vl);

    // 4) scores -> fp32 S  (batched over z=(b,h), K=64, KCH=1)
    gemm64<1, false><<<dim3(8, 4, BB * HH_), 256, SM_G>>>(
        qh2, ql2, kh2, kl2, nullptr, S, nullptr, nullptr, 1.0f,
        (long)LQ * DD,  (long)HD,          // A strides (b, h)
        (long)LKV * DD, (long)HD,          // B strides (b, h)
        (long)HH_ * LQ * LKV, (long)LQ * LKV);  // C strides (b, h)

    // 5) fused softmax + head-mean; probs emitted as bf16 hi/lo
    softmax_meanheads<<<BB * LQ, 256>>>(S, (__nv_bfloat162*)ph, (__nv_bfloat162*)pl,
                                        out + (long)BB * LQ * DD);

    // 6) ctx -> bf16 hi/lo directly in [B,Lq,D] layout
    ctx64<<<dim3(1, 4, BB * HH_), 256, SM_C>>>(ph, pl, vh, vl, ch, cl);

    // 7) out projection -> fp32 AO
    gemm64<16, false><<<dim3(8, 32, 1), 256, SM_G>>>(
        ch, cl, woh, wol, out_b, AO, nullptr, nullptr, 1.0f, 0,0, 0,0, 0,0);

    // 8) residual + LayerNorm
    residual_ln<<<BB * LQ, 256>>>(query, AO, gamma, beta, out);
}

// round 6
// speedup vs baseline: 2.6221x; 1.0094x over previous
#include <cuda_runtime.h>
#include <cuda_bf16.h>
#include <math.h>
#include <stdint.h>

// Problem constants
#define BB   8
#define LQ   512
#define LKV  1024
#define DD   1024
#define HH_  16
#define HD   64
#define LN_EPS 1e-5f

// ---------------------------------------------------------------------------
// Scratch (device globals: allocation-free per harness rules)
// ---------------------------------------------------------------------------
__device__ float g_V  [BB * LKV * DD];               // fp32 v proj
__device__ float g_S  [(size_t)BB * HH_ * LQ * LKV]; // fp32 scores
__device__ float g_AO [BB * LQ  * DD];               // fp32 attn_out
__device__ float2 g_stats[(size_t)BB * HH_ * LQ];    // per-row {max, 1/sum}

// bf16 hi/lo buffers
__device__ __align__(16) __nv_bfloat16 g_qh [BB * LQ  * DD], g_ql [BB * LQ  * DD];
__device__ __align__(16) __nv_bfloat16 g_kh [BB * LKV * DD], g_kl [BB * LKV * DD];
__device__ __align__(16) __nv_bfloat16 g_vh [BB * LKV * DD], g_vl [BB * LKV * DD];
__device__ __align__(16) __nv_bfloat16 g_wh [3 * DD * DD],   g_wl [3 * DD * DD];
__device__ __align__(16) __nv_bfloat16 g_woh[DD * DD],       g_wol[DD * DD];
__device__ __align__(16) __nv_bfloat16 g_qh2[BB * LQ  * DD], g_ql2[BB * LQ  * DD];
__device__ __align__(16) __nv_bfloat16 g_kh2[BB * LKV * DD], g_kl2[BB * LKV * DD];
__device__ __align__(16) __nv_bfloat16 g_ch [BB * LQ  * DD], g_cl [BB * LQ  * DD];

// ---------------------------------------------------------------------------
// Baseline-PTX tensor-core helpers (NO tcgen05 — compute_103 target!)
// ---------------------------------------------------------------------------
__device__ __forceinline__ uint32_t smem_u32(const void* p) {
    uint32_t a;
    asm("{ .reg .u64 t; cvta.to.shared.u64 t, %1; cvt.u32.u64 %0, t; }" : "=r"(a) : "l"(p));
    return a;
}
__device__ __forceinline__ void ldsm4(uint32_t& r0, uint32_t& r1, uint32_t& r2,
                                      uint32_t& r3, uint32_t a) {
    asm volatile("ldmatrix.sync.aligned.m8n8.x4.shared.b16 {%0,%1,%2,%3}, [%4];"
                 : "=r"(r0), "=r"(r1), "=r"(r2), "=r"(r3) : "r"(a));
}
__device__ __forceinline__ void mma_bf16(float* d, const uint32_t* a, const uint32_t* b) {
    asm volatile("mma.sync.aligned.m16n8k16.row.col.f32.bf16.bf16.f32 "
                 "{%0,%1,%2,%3},{%4,%5,%6,%7},{%8,%9},{%0,%1,%2,%3};"
                 : "+f"(d[0]), "+f"(d[1]), "+f"(d[2]), "+f"(d[3])
                 : "r"(a[0]), "r"(a[1]), "r"(a[2]), "r"(a[3]), "r"(b[0]), "r"(b[1]));
}
#define CP_ASYNC16(s, g) \
    asm volatile("cp.async.cg.shared.global [%0], [%1], 16;" :: "r"(s), "l"(g))
#define CP_COMMIT() asm volatile("cp.async.commit_group;" ::: "memory")
#define CP_WAIT1()  asm volatile("cp.async.wait_group 1;"  ::: "memory")

// 128B-row XOR swizzle: 16B chunk c (0..7), row r
__device__ __forceinline__ uint32_t sw128(int r, int c) {
    return (uint32_t)(r * 128 + ((c ^ (r & 7)) << 4));
}
__device__ __forceinline__ void bsplit(float v, __nv_bfloat16& h, __nv_bfloat16& l) {
    h = __float2bfloat16(v);
    l = __float2bfloat16(v - __bfloat162float(h));
}

// ---------------------------------------------------------------------------
// fp32 -> bf16 hi/lo split
// ---------------------------------------------------------------------------
__global__ void split_bf16(const float4* __restrict__ x,
                           __nv_bfloat162* __restrict__ hi,
                           __nv_bfloat162* __restrict__ lo, int n4)
{
    int i = blockIdx.x * blockDim.x + threadIdx.x;
    if (i >= n4) return;
    float4 v = x[i];
    __nv_bfloat16 h0, h1, h2, h3, l0, l1, l2, l3;
    bsplit(v.x, h0, l0); bsplit(v.y, h1, l1);
    bsplit(v.z, h2, l2); bsplit(v.w, h3, l3);
    hi[i * 2 + 0] = __halves2bfloat162(h0, h1);
    hi[i * 2 + 1] = __halves2bfloat162(h2, h3);
    lo[i * 2 + 0] = __halves2bfloat162(l0, l1);
    lo[i * 2 + 1] = __halves2bfloat162(l2, l3);
}

// ---------------------------------------------------------------------------
// Transpose + split V: fp32 V[b*Lkv + k][h*64 + n] -> Vt hi/lo [(b*16+h)*64 + n][k]
// ---------------------------------------------------------------------------
__global__ void transpose_split_v(const float* __restrict__ V,
                                  __nv_bfloat16* __restrict__ hi,
                                  __nv_bfloat16* __restrict__ lo)
{
    __shared__ float t[32][33];
    const int z = blockIdx.z, b = z >> 4, h = z & 15;
    const int k0 = blockIdx.x * 32, nn0 = blockIdx.y * 32;
    const int tx = threadIdx.x & 31, ty = threadIdx.x >> 5;
#pragma unroll
    for (int i = 0; i < 4; ++i) {
        int k = k0 + ty + i * 8;
        t[ty + i * 8][tx] = V[(((size_t)(b * 1024 + k)) << 10) + h * 64 + nn0 + tx];
    }
    __syncthreads();
#pragma unroll
    for (int i = 0; i < 4; ++i) {
        int n = nn0 + ty + i * 8;
        float v = t[tx][ty + i * 8];
        __nv_bfloat16 hh, ll;
        bsplit(v, hh, ll);
        size_t o = (((size_t)(z * 64 + n)) << 10) + k0 + tx;
        hi[o] = hh;
        lo[o] = ll;
    }
}

// ---------------------------------------------------------------------------
// Unified HMMA bf16x3 GEMM, BK=64, 3-stage cp.async, single sync per iter.
// ---------------------------------------------------------------------------
template<int KCH, bool SPLIT_OUT>
__global__ void __launch_bounds__(256, 2) gemm64(
    const __nv_bfloat16* __restrict__ Ahi, const __nv_bfloat16* __restrict__ Alo,
    const __nv_bfloat16* __restrict__ Bhi, const __nv_bfloat16* __restrict__ Blo,
    const float* __restrict__ bias, float* __restrict__ Cf,
    __nv_bfloat16* __restrict__ Chi, __nv_bfloat16* __restrict__ Clo, float scale,
    long sA0, long sA1, long sB0, long sB1, long sC0, long sC1)
{
    extern __shared__ __align__(16) char dynsm[];
    const uint32_t smBase = smem_u32(dynsm);

    const int tid  = threadIdx.x;
    const int lane = tid & 31;
    const int wid  = tid >> 5;
    const int wr   = wid >> 2;
    const int wc   = wid & 3;
    const int z    = blockIdx.z;
    const int m0   = blockIdx.y * 128;
    const int n0   = blockIdx.x * 128;
    const size_t aOff = (size_t)(z >> 4) * sA0 + (size_t)(z & 15) * sA1;
    const size_t bOff = (size_t)(z >> 4) * sB0 + (size_t)(z & 15) * sB1;
    const size_t cOff = (size_t)(z >> 4) * sC0 + (size_t)(z & 15) * sC1;

    const int rA  = lane & 15;
    const int cAh = lane >> 4;
    const int rBl = (lane & 7) + ((lane & 16) >> 1);
    const int cBh = (lane >> 3) & 1;

    float acc[4][4][4];
#pragma unroll
    for (int mt = 0; mt < 4; ++mt)
#pragma unroll
        for (int nt = 0; nt < 4; ++nt)
#pragma unroll
            for (int j = 0; j < 4; ++j) acc[mt][nt][j] = 0.f;

    auto prefetch = [&](int it, int stage) {
        const int part = it / KCH;
        const int ko   = (it % KCH) << 6;
        const __nv_bfloat16* Ap = (part == 2) ? Alo : Ahi;
        const __nv_bfloat16* Bp = (part == 1) ? Blo : Bhi;
        const uint32_t as = smBase + (uint32_t)stage * 32768u;
        const uint32_t bs = as + 16384u;
#pragma unroll
        for (int i = 0; i < 4; ++i) {
            int q = i * 256 + tid;
            int r = q >> 3, c = q & 7;
            CP_ASYNC16(as + sw128(r, c),
                       Ap + aOff + (((size_t)(m0 + r)) << 10) + ko + c * 8);
            CP_ASYNC16(bs + sw128(r, c),
                       Bp + bOff + (((size_t)(n0 + r)) << 10) + ko + c * 8);
        }
        CP_COMMIT();
    };

    const int NIT = 3 * KCH;
    prefetch(0, 0);
    prefetch(1, 1);

    for (int it = 0; it < NIT; ++it) {
        CP_WAIT1();
        __syncthreads();
        if (it + 2 < NIT) prefetch(it + 2, (it + 2) % 3);
        else CP_COMMIT();

        const uint32_t aT = smBase + (uint32_t)(it % 3) * 32768u;
        const uint32_t bT = aT + 16384u;

#pragma unroll
        for (int ks = 0; ks < 4; ++ks) {
            uint32_t af[4][4];
            uint32_t bf[4][2];
#pragma unroll
            for (int mt = 0; mt < 4; ++mt) {
                int r = wr * 64 + mt * 16 + rA;
                ldsm4(af[mt][0], af[mt][1], af[mt][2], af[mt][3],
                      aT + sw128(r, ks * 2 + cAh));
            }
#pragma unroll
            for (int tp = 0; tp < 2; ++tp) {
                int r = wc * 32 + tp * 16 + rBl;
                uint32_t x0, x1, x2, x3;
                ldsm4(x0, x1, x2, x3, bT + sw128(r, ks * 2 + cBh));
                bf[tp * 2][0] = x0;     bf[tp * 2][1] = x1;
                bf[tp * 2 + 1][0] = x2; bf[tp * 2 + 1][1] = x3;
            }
#pragma unroll
            for (int mt = 0; mt < 4; ++mt)
#pragma unroll
                for (int nt = 0; nt < 4; ++nt)
                    mma_bf16(acc[mt][nt], af[mt], bf[nt]);
        }
    }
    __syncthreads();

#pragma unroll
    for (int mt = 0; mt < 4; ++mt) {
        const int row = m0 + wr * 64 + mt * 16 + (lane >> 2);
#pragma unroll
        for (int nt = 0; nt < 4; ++nt) {
            const int col = n0 + wc * 32 + nt * 8 + (lane & 3) * 2;
            const float b0 = bias ? bias[col]     : 0.f;
            const float b1 = bias ? bias[col + 1] : 0.f;
            const float v0 = (acc[mt][nt][0] + b0) * scale;
            const float v1 = (acc[mt][nt][1] + b1) * scale;
            const float v2 = (acc[mt][nt][2] + b0) * scale;
            const float v3 = (acc[mt][nt][3] + b1) * scale;
            const size_t i0 = cOff + ((size_t)row << 10) + col;
            const size_t i1 = i0 + (8 << 10);
            if (SPLIT_OUT) {
                __nv_bfloat16 h0, h1, h2, h3, l0, l1, l2, l3;
                bsplit(v0, h0, l0); bsplit(v1, h1, l1);
                bsplit(v2, h2, l2); bsplit(v3, h3, l3);
                *(__nv_bfloat162*)(Chi + i0) = __halves2bfloat162(h0, h1);
                *(__nv_bfloat162*)(Clo + i0) = __halves2bfloat162(l0, l1);
                *(__nv_bfloat162*)(Chi + i1) = __halves2bfloat162(h2, h3);
                *(__nv_bfloat162*)(Clo + i1) = __halves2bfloat162(l2, l3);
            } else {
                Cf[i0] = v0; Cf[i0 + 1] = v1;
                Cf[i1] = v2; Cf[i1 + 1] = v3;
            }
        }
    }
}

// ---------------------------------------------------------------------------
// Softmax stats + head-mean. One block per (b,q); loops over 16 heads.
// Writes per-row {max, 1/sum} and the attn_weights mean. NO P materialization.
// ---------------------------------------------------------------------------
__global__ void softmax_stats(const float* __restrict__ S,
                              float2* __restrict__ stats,
                              float* __restrict__ mean_out)
{
    __shared__ float red[8];
    __shared__ float bcast;
    const int bq = blockIdx.x;
    const int b = bq >> 9, q = bq & 511;
    const int tid = threadIdx.x;

    float4 macc = make_float4(0.f, 0.f, 0.f, 0.f);

#pragma unroll 1
    for (int h = 0; h < HH_; ++h) {
        const size_t rowe = ((size_t)(b * 16 + h) * 512 + q) << 10;
        float4 v = *(const float4*)(S + rowe + tid * 4);

        float m = fmaxf(fmaxf(v.x, v.y), fmaxf(v.z, v.w));
#pragma unroll
        for (int o = 16; o; o >>= 1) m = fmaxf(m, __shfl_xor_sync(0xffffffffu, m, o));
        if ((tid & 31) == 0) red[tid >> 5] = m;
        __syncthreads();
        if (tid < 8) {
            m = red[tid];
#pragma unroll
            for (int o = 4; o; o >>= 1) m = fmaxf(m, __shfl_xor_sync(0xffu, m, o));
            if (tid == 0) bcast = m;
        }
        __syncthreads();
        m = bcast;

        v.x = __expf(v.x - m); v.y = __expf(v.y - m);
        v.z = __expf(v.z - m); v.w = __expf(v.w - m);
        float s = (v.x + v.y) + (v.z + v.w);
#pragma unroll
        for (int o = 16; o; o >>= 1) s += __shfl_xor_sync(0xffffffffu, s, o);
        __syncthreads();
        if ((tid & 31) == 0) red[tid >> 5] = s;
        __syncthreads();
        if (tid < 8) {
            s = red[tid];
#pragma unroll
            for (int o = 4; o; o >>= 1) s += __shfl_xor_sync(0xffu, s, o);
            if (tid == 0) bcast = s;
        }
        __syncthreads();
        const float inv = 1.0f / bcast;
        if (tid == 0) stats[(size_t)(b * 16 + h) * 512 + q] = make_float2(m, inv);

        macc.x += v.x * inv; macc.y += v.y * inv;
        macc.z += v.z * inv; macc.w += v.w * inv;
        __syncthreads();
    }

    const float inv16 = 1.0f / HH_;
    macc.x *= inv16; macc.y *= inv16; macc.z *= inv16; macc.w *= inv16;
    *(float4*)(mean_out + (((size_t)bq) << 10) + tid * 4) = macc;
}

// ---------------------------------------------------------------------------
// Fused ctx: per z=(b,h), q-tile 128: reads fp32 S, applies exp*(inv) in-flight,
// splits P to bf16 hi/lo in SMEM, then 3-term MMA against Vt hi/lo chunks.
// 512 threads (16 warps: 4 m x 4 n; warp tile 32x16). 16 kv-chunks of 64.
// SMEM: P double-buffer 2x32KB + V triple-buffer 3x16KB = 112KB.
// Writes ctx as bf16 hi/lo at [b*512+row][h*64+col].
// ---------------------------------------------------------------------------
__global__ void __launch_bounds__(512) ctx_fused(
    const float* __restrict__ S, const float2* __restrict__ stats,
    const __nv_bfloat16* __restrict__ Vhi, const __nv_bfloat16* __restrict__ Vlo,
    __nv_bfloat16* __restrict__ Chi, __nv_bfloat16* __restrict__ Clo)
{
    extern __shared__ __align__(16) char dynsm[];
    const uint32_t smBase = smem_u32(dynsm);   // P: 2*32768; V: +65536, 3*16384

    const int tid  = threadIdx.x;
    const int lane = tid & 31;
    const int wid  = tid >> 5;
    const int wr   = wid >> 2;   // 0..3 (32 rows each)
    const int wc   = wid & 3;    // 0..3 (16 cols each)
    const int z    = blockIdx.z, b = z >> 4, h = z & 15;
    const int m0   = blockIdx.y * 128;
    const size_t sOff  = ((size_t)z * 512 + m0) << 10;   // S[z][m0][0]
    const size_t vOff  = ((size_t)z * 64) << 10;         // Vt[z*64][0]
    const int    stOff = z * 512 + m0;

    const int rA  = lane & 15;
    const int cAh = lane >> 4;
    const int rBl = (lane & 7) + ((lane & 16) >> 1);
    const int cBh = (lane >> 3) & 1;

    float acc[2][2][4];
#pragma unroll
    for (int mt = 0; mt < 2; ++mt)
#pragma unroll
        for (int nt = 0; nt < 2; ++nt)
#pragma unroll
            for (int j = 0; j < 4; ++j) acc[mt][nt][j] = 0.f;

    // per-thread S mapping: idx = i*512 + tid -> row = idx>>4, f4col = idx&15
    float4 sreg[4];
    auto ldS = [&](int kc) {
#pragma unroll
        for (int i = 0; i < 4; ++i) {
            int idx = i * 512 + tid;
            int row = idx >> 4, f4 = idx & 15;
            sreg[i] = __ldg((const float4*)(S + sOff + ((size_t)row << 10) +
                                            (kc << 6) + f4 * 4));
        }
    };
    auto cpV = [&](int kc) {
        const uint32_t vs = smBase + 65536u + (uint32_t)(kc % 3) * 16384u;
        // 64 rows x 8 chunks = 512 chunks each for Vhi and Vlo; 1 per thread
        int r = tid >> 3, c = tid & 7;
        CP_ASYNC16(vs + sw128(r, c), Vhi + vOff + ((size_t)r << 10) + (kc << 6) + c * 8);
        CP_ASYNC16(vs + 8192u + sw128(r, c),
                   Vlo + vOff + ((size_t)r << 10) + (kc << 6) + c * 8);
        CP_COMMIT();
    };

    // prologue
    ldS(0);
    cpV(0);
    cpV(1);

    for (int kc = 0; kc < 16; ++kc) {
        // convert current S regs -> P hi/lo smem (buffer kc&1)
        const uint32_t pB = smBase + (uint32_t)(kc & 1) * 32768u;
#pragma unroll
        for (int i = 0; i < 4; ++i) {
            int idx = i * 512 + tid;
            int row = idx >> 4, f4 = idx & 15;
            float2 st = __ldg((const float2*)&stats[stOff + row]);
            float p0 = __expf(sreg[i].x - st.x) * st.y;
            float p1 = __expf(sreg[i].y - st.x) * st.y;
            float p2 = __expf(sreg[i].z - st.x) * st.y;
            float p3 = __expf(sreg[i].w - st.x) * st.y;
            __nv_bfloat16 h0, h1, h2, h3, l0, l1, l2, l3;
            bsplit(p0, h0, l0); bsplit(p1, h1, l1);
            bsplit(p2, h2, l2); bsplit(p3, h3, l3);
            uint32_t off = sw128(row, f4 >> 1) + (f4 & 1) * 8;
            __nv_bfloat162 ph0 = __halves2bfloat162(h0, h1);
            __nv_bfloat162 ph1 = __halves2bfloat162(h2, h3);
            __nv_bfloat162 pl0 = __halves2bfloat162(l0, l1);
            __nv_bfloat162 pl1 = __halves2bfloat162(l2, l3);
            asm volatile("st.shared.v2.b32 [%0], {%1, %2};" ::
                         "r"(pB + off), "r"(*(uint32_t*)&ph0), "r"(*(uint32_t*)&ph1)
                         : "memory");
            asm volatile("st.shared.v2.b32 [%0], {%1, %2};" ::
                         "r"(pB + 16384u + off), "r"(*(uint32_t*)&pl0), "r"(*(uint32_t*)&pl1)
                         : "memory");
        }
        if (kc + 1 < 16) ldS(kc + 1);   // overlap next S load with MMA

        CP_WAIT1();                      // V(kc) resident
        __syncthreads();                 // P(kc) visible; V buf (kc+2)%3 free
        if (kc + 2 < 16) cpV(kc + 2);
        else CP_COMMIT();                // keep group accounting uniform

        const uint32_t phT = smBase + (uint32_t)(kc & 1) * 32768u;
        const uint32_t plT = phT + 16384u;
        const uint32_t vhT = smBase + 65536u + (uint32_t)(kc % 3) * 16384u;
        const uint32_t vlT = vhT + 8192u;

#pragma unroll
        for (int ks = 0; ks < 4; ++ks) {
            uint32_t ah[2][4], al[2][4];
            uint32_t bh[2][2], bl[2][2];
#pragma unroll
            for (int mt = 0; mt < 2; ++mt) {
                int r = wr * 32 + mt * 16 + rA;
                ldsm4(ah[mt][0], ah[mt][1], ah[mt][2], ah[mt][3],
                      phT + sw128(r, ks * 2 + cAh));
                ldsm4(al[mt][0], al[mt][1], al[mt][2], al[mt][3],
                      plT + sw128(r, ks * 2 + cAh));
            }
            {
                int r = wc * 16 + rBl;
                uint32_t x0, x1, x2, x3;
                ldsm4(x0, x1, x2, x3, vhT + sw128(r, ks * 2 + cBh));
                bh[0][0] = x0; bh[0][1] = x1; bh[1][0] = x2; bh[1][1] = x3;
                ldsm4(x0, x1, x2, x3, vlT + sw128(r, ks * 2 + cBh));
                bl[0][0] = x0; bl[0][1] = x1; bl[1][0] = x2; bl[1][1] = x3;
            }
#pragma unroll
            for (int mt = 0; mt < 2; ++mt)
#pragma unroll
                for (int nt = 0; nt < 2; ++nt) {
                    mma_bf16(acc[mt][nt], ah[mt], bh[nt]);
                    mma_bf16(acc[mt][nt], ah[mt], bl[nt]);
                    mma_bf16(acc[mt][nt], al[mt], bh[nt]);
                }
        }
    }

    // epilogue: split ctx to bf16 hi/lo at [b*512+row][h*64+col]
#pragma unroll
    for (int mt = 0; mt < 2; ++mt) {
        const int row = m0 + wr * 32 + mt * 16 + (lane >> 2);
#pragma unroll
        for (int nt = 0; nt < 2; ++nt) {
            const int col = h * 64 + wc * 16 + nt * 8 + (lane & 3) * 2;
            const size_t i0 = (((size_t)(b * 512 + row)) << 10) + col;
            const size_t i1 = i0 + (8 << 10);
            __nv_bfloat16 h0, h1, h2, h3, l0, l1, l2, l3;
            bsplit(acc[mt][nt][0], h0, l0); bsplit(acc[mt][nt][1], h1, l1);
            bsplit(acc[mt][nt][2], h2, l2); bsplit(acc[mt][nt][3], h3, l3);
            *(__nv_bfloat162*)(Chi + i0) = __halves2bfloat162(h0, h1);
            *(__nv_bfloat162*)(Clo + i0) = __halves2bfloat162(l0, l1);
            *(__nv_bfloat162*)(Chi + i1) = __halves2bfloat162(h2, h3);
            *(__nv_bfloat162*)(Clo + i1) = __halves2bfloat162(l2, l3);
        }
    }
}

// ---------------------------------------------------------------------------
// out = LayerNorm(query + attn_out) * gamma + beta.  One block per row.
// ---------------------------------------------------------------------------
__global__ void residual_ln(const float* __restrict__ q, const float* __restrict__ ao,
                            const float* __restrict__ gamma, const float* __restrict__ beta,
                            float* __restrict__ out)
{
    __shared__ float red[8];
    __shared__ float bcast;
    const long row = blockIdx.x;
    const int tid = threadIdx.x;

    float4 qa = *(const float4*)&q [row * DD + tid * 4];
    float4 aa = *(const float4*)&ao[row * DD + tid * 4];
    float x0 = qa.x + aa.x, x1 = qa.y + aa.y, x2 = qa.z + aa.z, x3 = qa.w + aa.w;

    float s = (x0 + x1) + (x2 + x3);
#pragma unroll
    for (int o = 16; o; o >>= 1) s += __shfl_xor_sync(0xffffffffu, s, o);
    if ((tid & 31) == 0) red[tid >> 5] = s;
    __syncthreads();
    if (tid < 8) {
        s = red[tid];
#pragma unroll
        for (int o = 4; o; o >>= 1) s += __shfl_xor_sync(0xffu, s, o);
        if (tid == 0) bcast = s;
    }
    __syncthreads();
    const float mu = bcast * (1.0f / DD);

    float d0 = x0 - mu, d1 = x1 - mu, d2 = x2 - mu, d3 = x3 - mu;
    float sq = (d0 * d0 + d1 * d1) + (d2 * d2 + d3 * d3);
#pragma unroll
    for (int o = 16; o; o >>= 1) sq += __shfl_xor_sync(0xffffffffu, sq, o);
    __syncthreads();
    if ((tid & 31) == 0) red[tid >> 5] = sq;
    __syncthreads();
    if (tid < 8) {
        sq = red[tid];
#pragma unroll
        for (int o = 4; o; o >>= 1) sq += __shfl_xor_sync(0xffu, sq, o);
        if (tid == 0) bcast = sq;
    }
    __syncthreads();
    const float rstd = rsqrtf(bcast * (1.0f / DD) + LN_EPS);

    float4 g = *(const float4*)&gamma[tid * 4];
    float4 be = *(const float4*)&beta[tid * 4];
    float4 o4;
    o4.x = d0 * rstd * g.x + be.x;
    o4.y = d1 * rstd * g.y + be.y;
    o4.z = d2 * rstd * g.z + be.z;
    o4.w = d3 * rstd * g.w + be.w;
    *(float4*)&out[row * DD + tid * 4] = o4;
}

// ---------------------------------------------------------------------------
extern "C" void kernel_launch(void* const* d_in, const int* in_sizes, int n_in,
                              void* d_out, int out_size)
{
    const float* query = (const float*)d_in[0];
    const float* key_  = (const float*)d_in[1];
    const float* value = (const float*)d_in[2];
    const float* in_w  = (const float*)d_in[3];
    const float* in_b  = (const float*)d_in[4];
    const float* out_w = (const float*)d_in[5];
    const float* out_b = (const float*)d_in[6];
    const float* gamma = (const float*)d_in[7];
    const float* beta  = (const float*)d_in[8];
    float* out = (float*)d_out;

    float *V, *S, *AO;
    float2* ST;
    cudaGetSymbolAddress((void**)&V,  g_V);
    cudaGetSymbolAddress((void**)&S,  g_S);
    cudaGetSymbolAddress((void**)&AO, g_AO);
    cudaGetSymbolAddress((void**)&ST, g_stats);

    __nv_bfloat16 *qh, *ql, *kh, *kl, *vh, *vl, *wh, *wl, *woh, *wol;
    __nv_bfloat16 *qh2, *ql2, *kh2, *kl2, *ch, *cl;
    cudaGetSymbolAddress((void**)&qh,  g_qh);  cudaGetSymbolAddress((void**)&ql,  g_ql);
    cudaGetSymbolAddress((void**)&kh,  g_kh);  cudaGetSymbolAddress((void**)&kl,  g_kl);
    cudaGetSymbolAddress((void**)&vh,  g_vh);  cudaGetSymbolAddress((void**)&vl,  g_vl);
    cudaGetSymbolAddress((void**)&wh,  g_wh);  cudaGetSymbolAddress((void**)&wl,  g_wl);
    cudaGetSymbolAddress((void**)&woh, g_woh); cudaGetSymbolAddress((void**)&wol, g_wol);
    cudaGetSymbolAddress((void**)&qh2, g_qh2); cudaGetSymbolAddress((void**)&ql2, g_ql2);
    cudaGetSymbolAddress((void**)&kh2, g_kh2); cudaGetSymbolAddress((void**)&kl2, g_kl2);
    cudaGetSymbolAddress((void**)&ch,  g_ch);  cudaGetSymbolAddress((void**)&cl,  g_cl);

    const int SM_G = 3 * 32768;
    const int SM_X = 2 * 32768 + 3 * 16384;   // ctx_fused: 112 KB
    cudaFuncSetAttribute(gemm64<16, true>,  cudaFuncAttributeMaxDynamicSharedMemorySize, SM_G);
    cudaFuncSetAttribute(gemm64<16, false>, cudaFuncAttributeMaxDynamicSharedMemorySize, SM_G);
    cudaFuncSetAttribute(gemm64<1,  false>, cudaFuncAttributeMaxDynamicSharedMemorySize, SM_G);
    cudaFuncSetAttribute(ctx_fused, cudaFuncAttributeMaxDynamicSharedMemorySize, SM_X);

    const float qscale = 0.125f;

    auto launch_split = [](const float* x, __nv_bfloat16* h, __nv_bfloat16* l, long n) {
        int n4 = (int)(n / 4);
        split_bf16<<<(n4 + 255) / 256, 256>>>((const float4*)x, (__nv_bfloat162*)h,
                                              (__nv_bfloat162*)l, n4);
    };

    // 1) split inputs + weights
    launch_split(query, qh, ql, (long)BB * LQ  * DD);
    launch_split(key_,  kh, kl, (long)BB * LKV * DD);
    launch_split(value, vh, vl, (long)BB * LKV * DD);
    launch_split(in_w,  wh, wl, 3L * DD * DD);
    launch_split(out_w, woh, wol, (long)DD * DD);

    // 2) Q/K projections -> bf16 hi/lo directly; V projection -> fp32
    gemm64<16, true><<<dim3(8, 32, 1), 256, SM_G>>>(
        qh, ql, wh, wl, in_b, nullptr, qh2, ql2, qscale, 0,0, 0,0, 0,0);
    gemm64<16, true><<<dim3(8, 64, 1), 256, SM_G>>>(
        kh, kl, wh + (long)DD*DD, wl + (long)DD*DD, in_b + DD,
        nullptr, kh2, kl2, 1.0f, 0,0, 0,0, 0,0);
    gemm64<16, false><<<dim3(8, 64, 1), 256, SM_G>>>(
        vh, vl, wh + 2L*DD*DD, wl + 2L*DD*DD, in_b + 2*DD,
        V, nullptr, nullptr, 1.0f, 0,0, 0,0, 0,0);

    // 3) transpose + split V into head-major Vt
    transpose_split_v<<<dim3(LKV / 32, HD / 32, BB * HH_), 256>>>(V, vh, vl);

    // 4) scores -> fp32 S
    gemm64<1, false><<<dim3(8, 4, BB * HH_), 256, SM_G>>>(
        qh2, ql2, kh2, kl2, nullptr, S, nullptr, nullptr, 1.0f,
        (long)LQ * DD,  (long)HD,
        (long)LKV * DD, (long)HD,
        (long)HH_ * LQ * LKV, (long)LQ * LKV);

    // 5) softmax stats + head-mean (no P materialization)
    softmax_stats<<<BB * LQ, 256>>>(S, ST, out + (long)BB * LQ * DD);

    // 6) fused exp/normalize/split + ctx MMA -> bf16 hi/lo ctx
    ctx_fused<<<dim3(1, 4, BB * HH_), 512, SM_X>>>(S, ST, vh, vl, ch, cl);

    // 7) out projection -> fp32 AO
    gemm64<16, false><<<dim3(8, 32, 1), 256, SM_G>>>(
        ch, cl, woh, wol, out_b, AO, nullptr, nullptr, 1.0f, 0,0, 0,0, 0,0);

    // 8) residual + LayerNorm
    residual_ln<<<BB * LQ, 256>>>(query, AO, gamma, beta, out);
}